// round 1
// baseline (speedup 1.0000x reference)
#include <cuda_runtime.h>
#include <math.h>

// Problem constants
#define BB      256
#define NTOK    197
#define CC      768
#define POOL    1024
#define PLEN    8
#define KSEL    8
#define OUTROWS 261   // 1 + KSEL*PLEN + (NTOK-1)
#define PROMPTED_ELEMS ((size_t)BB * OUTROWS * CC)   // 51,314,688

// Scratch (device globals — no allocation allowed)
__device__ float g_xnorm[BB * CC];          // normalized mean embedding  [B, C]
__device__ float g_pnorm[POOL * CC];        // normalized prompt keys     [P, C]
__device__ float g_sim[BB * POOL];          // similarity matrix          [B, P]
__device__ float g_proj[POOL * PLEN * CC];  // projected prompts (all)    [P*L, C]
__device__ int   g_idx[BB * KSEL];          // top-k indices
__device__ float g_topsum[BB];              // per-batch top-k value sum

// ---------------------------------------------------------------------------
// Kernel 1: x_mean = mean(x_embed, axis=1); x_norm = l2_normalize(x_mean)
// one block per batch, 768 threads (one per channel)
// ---------------------------------------------------------------------------
__global__ void mean_norm_kernel(const float* __restrict__ x) {
    int b = blockIdx.x;
    int c = threadIdx.x;
    const float* xp = x + (size_t)b * NTOK * CC + c;
    float s = 0.0f;
    #pragma unroll 4
    for (int n = 0; n < NTOK; n++) s += xp[(size_t)n * CC];
    float m = s / (float)NTOK;

    __shared__ float sh[CC];
    sh[c] = m * m;
    __syncthreads();
    if (c < 256) sh[c] += sh[c + 256] + sh[c + 512];
    __syncthreads();
    for (int off = 128; off > 0; off >>= 1) {
        if (c < off) sh[c] += sh[c + off];
        __syncthreads();
    }
    __shared__ float rinv;
    if (c == 0) rinv = rsqrtf(fmaxf(sh[0], 1e-12f));
    __syncthreads();
    g_xnorm[b * CC + c] = m * rinv;
}

// ---------------------------------------------------------------------------
// Kernel 2: prompt_norm = l2_normalize(prompt_key, axis=1)
// ---------------------------------------------------------------------------
__global__ void key_norm_kernel(const float* __restrict__ pk) {
    int p = blockIdx.x;
    int c = threadIdx.x;
    float v = pk[(size_t)p * CC + c];

    __shared__ float sh[CC];
    sh[c] = v * v;
    __syncthreads();
    if (c < 256) sh[c] += sh[c + 256] + sh[c + 512];
    __syncthreads();
    for (int off = 128; off > 0; off >>= 1) {
        if (c < off) sh[c] += sh[c + off];
        __syncthreads();
    }
    __shared__ float rinv;
    if (c == 0) rinv = rsqrtf(fmaxf(sh[0], 1e-12f));
    __syncthreads();
    g_pnorm[p * CC + c] = v * rinv;
}

// ---------------------------------------------------------------------------
// Generic fp32 SIMT NT-GEMM: C[m,n] = sum_k A[m,k] * B[n,k]
//   A: [M,K] row-major, B: [N,K] row-major.
//   EPI=true adds bias[n] + A[m,n] (residual; requires N==K).
//   BM==BN, BM*BK == 1024, 256 threads, thread tile TM x TN.
// ---------------------------------------------------------------------------
template<int BM, int BN, int BK, int TM, int TN, bool EPI>
__global__ __launch_bounds__(256)
void gemm_nt(const float* __restrict__ A, const float* __restrict__ Bm,
             const float* __restrict__ bias, float* __restrict__ Cm,
             int M, int Nn, int K) {
    static_assert(BM == BN, "loader assumes BM==BN");
    static_assert(BM * BK == 1024, "256 threads x float4");
    __shared__ float As[BK][BM];
    __shared__ float Bs[BK][BN];

    const int tid = threadIdx.x;
    const int tx  = tid % (BN / TN);
    const int ty  = tid / (BN / TN);
    const int m0  = blockIdx.y * BM;
    const int n0  = blockIdx.x * BN;

    const int TPR  = BK / 4;            // threads per tile-row (float4)
    const int lrow = tid / TPR;         // 0..BM-1
    const int lk   = (tid % TPR) * 4;

    float acc[TM][TN];
    #pragma unroll
    for (int i = 0; i < TM; i++)
        #pragma unroll
        for (int j = 0; j < TN; j++) acc[i][j] = 0.0f;

    for (int k0 = 0; k0 < K; k0 += BK) {
        float4 av = *(const float4*)(A  + (size_t)(m0 + lrow) * K + k0 + lk);
        float4 bv = *(const float4*)(Bm + (size_t)(n0 + lrow) * K + k0 + lk);
        __syncthreads();
        As[lk + 0][lrow] = av.x; As[lk + 1][lrow] = av.y;
        As[lk + 2][lrow] = av.z; As[lk + 3][lrow] = av.w;
        Bs[lk + 0][lrow] = bv.x; Bs[lk + 1][lrow] = bv.y;
        Bs[lk + 2][lrow] = bv.z; Bs[lk + 3][lrow] = bv.w;
        __syncthreads();

        #pragma unroll
        for (int kk = 0; kk < BK; kk++) {
            float a[TM], bb[TN];
            #pragma unroll
            for (int i = 0; i < TM; i += 4)
                *(float4*)&a[i] = *(const float4*)&As[kk][ty * TM + i];
            #pragma unroll
            for (int j = 0; j < TN; j += 4)
                *(float4*)&bb[j] = *(const float4*)&Bs[kk][tx * TN + j];
            #pragma unroll
            for (int i = 0; i < TM; i++)
                #pragma unroll
                for (int j = 0; j < TN; j++)
                    acc[i][j] = fmaf(a[i], bb[j], acc[i][j]);
        }
    }

    #pragma unroll
    for (int i = 0; i < TM; i++) {
        int m = m0 + ty * TM + i;
        #pragma unroll
        for (int j = 0; j < TN; j += 4) {
            int n = n0 + tx * TN + j;
            float4 v;
            v.x = acc[i][j + 0]; v.y = acc[i][j + 1];
            v.z = acc[i][j + 2]; v.w = acc[i][j + 3];
            if (EPI) {
                const float* ar = A + (size_t)m * K + n;  // residual (N==K)
                v.x += bias[n + 0] + ar[0];
                v.y += bias[n + 1] + ar[1];
                v.z += bias[n + 2] + ar[2];
                v.w += bias[n + 3] + ar[3];
            }
            *(float4*)&Cm[(size_t)m * Nn + n] = v;
        }
    }
}

// ---------------------------------------------------------------------------
// Kernel: per-batch top-8 of similarity (descending, ties -> smaller index,
// matching lax.top_k) + sum of selected values.
// ---------------------------------------------------------------------------
__global__ void topk_kernel() {
    int b = blockIdx.x;
    int t = threadIdx.x;  // 256 threads
    __shared__ float vals[POOL];
    __shared__ float rv[256];
    __shared__ int   ri[256];

    for (int p = t; p < POOL; p += 256) vals[p] = g_sim[b * POOL + p];
    __syncthreads();

    float tsum = 0.0f;
    for (int it = 0; it < KSEL; it++) {
        float bvv = -1e30f; int bii = 0x7fffffff;
        for (int p = t; p < POOL; p += 256) {
            float v = vals[p];
            if (v > bvv || (v == bvv && p < bii)) { bvv = v; bii = p; }
        }
        rv[t] = bvv; ri[t] = bii;
        __syncthreads();
        for (int off = 128; off > 0; off >>= 1) {
            if (t < off) {
                float v2 = rv[t + off]; int i2 = ri[t + off];
                if (v2 > rv[t] || (v2 == rv[t] && i2 < ri[t])) { rv[t] = v2; ri[t] = i2; }
            }
            __syncthreads();
        }
        if (t == 0) {
            g_idx[b * KSEL + it] = ri[0];
            tsum += rv[0];
            vals[ri[0]] = -1e30f;
        }
        __syncthreads();
    }
    if (t == 0) g_topsum[b] = tsum;
}

// ---------------------------------------------------------------------------
// Kernel: deterministic final reduce_sim = sum(topsum)/B  -> out[PROMPTED]
// ---------------------------------------------------------------------------
__global__ void reduce_sim_kernel(float* __restrict__ out) {
    __shared__ float sh[256];
    int t = threadIdx.x;
    sh[t] = g_topsum[t];
    __syncthreads();
    for (int off = 128; off > 0; off >>= 1) {
        if (t < off) sh[t] += sh[t + off];
        __syncthreads();
    }
    if (t == 0) out[PROMPTED_ELEMS] = sh[0] / (float)BB;
}

// ---------------------------------------------------------------------------
// Kernel: assemble output: [cls token | gathered projected prompts | rest]
// one block per (row, batch); 192 threads x float4 = 768 floats
// ---------------------------------------------------------------------------
__global__ void assemble_kernel(const float* __restrict__ x, float* __restrict__ out) {
    int r = blockIdx.x;   // 0..260
    int b = blockIdx.y;   // 0..255
    int t = threadIdx.x;  // 0..191

    const float4* src;
    if (r == 0) {
        src = (const float4*)(x + (size_t)b * NTOK * CC);
    } else if (r <= KSEL * PLEN) {
        int j = r - 1;
        int k = j >> 3, l = j & 7;
        int pid = g_idx[b * KSEL + k];
        src = (const float4*)(g_proj + ((size_t)pid * PLEN + l) * CC);
    } else {
        src = (const float4*)(x + ((size_t)b * NTOK + (r - KSEL * PLEN)) * CC);
    }
    float4 v = src[t];
    ((float4*)(out + ((size_t)b * OUTROWS + r) * CC))[t] = v;
}

// ---------------------------------------------------------------------------
extern "C" void kernel_launch(void* const* d_in, const int* in_sizes, int n_in,
                              void* d_out, int out_size) {
    const float* x_embed = (const float*)d_in[0];
    const float* prompt  = (const float*)d_in[1];
    const float* pkey    = (const float*)d_in[2];
    const float* proj_w  = (const float*)d_in[3];
    const float* proj_b  = (const float*)d_in[4];
    float* out = (float*)d_out;

    float *p_xnorm, *p_pnorm, *p_sim, *p_proj;
    cudaGetSymbolAddress((void**)&p_xnorm, g_xnorm);
    cudaGetSymbolAddress((void**)&p_pnorm, g_pnorm);
    cudaGetSymbolAddress((void**)&p_sim,   g_sim);
    cudaGetSymbolAddress((void**)&p_proj,  g_proj);

    // 1) Project ALL 1024*8 prompt rows (independent of top-k; half the FLOPs
    //    of projecting gathered rows):  g_proj = prompt @ W^T + b + prompt
    {
        dim3 grid(CC / 128, (POOL * PLEN) / 128);
        gemm_nt<128, 128, 8, 8, 8, true><<<grid, 256>>>(
            prompt, proj_w, proj_b, p_proj, POOL * PLEN, CC, CC);
    }

    // 2) Normalized mean embedding + normalized keys
    mean_norm_kernel<<<BB, CC>>>(x_embed);
    key_norm_kernel<<<POOL, CC>>>(pkey);

    // 3) similarity = x_norm @ prompt_norm^T   [256, 1024]
    {
        dim3 grid(POOL / 64, BB / 64);
        gemm_nt<64, 64, 16, 4, 4, false><<<grid, 256>>>(
            p_xnorm, p_pnorm, nullptr, p_sim, BB, POOL, CC);
    }

    // 4) top-8 per batch (+ per-batch top-value sums)
    topk_kernel<<<BB, 256>>>();

    // 5) reduce_sim scalar (deterministic tree reduce)
    reduce_sim_kernel<<<1, 256>>>(out);

    // 6) assemble prompted output
    {
        dim3 grid(OUTROWS, BB);
        assemble_kernel<<<grid, 192>>>(x_embed, out);
    }
}

// round 2
// speedup vs baseline: 1.8537x; 1.8537x over previous
#include <cuda_runtime.h>
#include <math.h>
#include <stdint.h>

// Problem constants
#define BB      256
#define NTOK    197
#define CC      768
#define POOL    1024
#define PLEN    8
#define KSEL    8
#define OUTROWS 261
#define PROMPTED_ELEMS ((size_t)BB * OUTROWS * CC)

// Scratch (device globals)
__device__ float g_xnorm[BB * CC];
__device__ float g_pnorm[POOL * CC];
__device__ float g_sim[BB * POOL];
__device__ float g_proj[POOL * PLEN * CC];
__device__ int   g_idx[BB * KSEL];
__device__ float g_topsum[BB];

// ---------------------------------------------------------------------------
__device__ __forceinline__ uint32_t f2tf32(float f) {
    uint32_t r;
    asm("cvt.rna.tf32.f32 %0, %1;" : "=r"(r) : "f"(f));
    return r;
}

// ---------------------------------------------------------------------------
// Kernel 1: x_mean = mean(x_embed, axis=1); x_norm = l2_normalize(x_mean)
// ---------------------------------------------------------------------------
__global__ void mean_norm_kernel(const float* __restrict__ x) {
    int b = blockIdx.x;
    int c = threadIdx.x;
    const float* xp = x + (size_t)b * NTOK * CC + c;
    float s = 0.0f;
    #pragma unroll 4
    for (int n = 0; n < NTOK; n++) s += xp[(size_t)n * CC];
    float m = s / (float)NTOK;

    __shared__ float sh[CC];
    sh[c] = m * m;
    __syncthreads();
    if (c < 256) sh[c] += sh[c + 256] + sh[c + 512];
    __syncthreads();
    for (int off = 128; off > 0; off >>= 1) {
        if (c < off) sh[c] += sh[c + off];
        __syncthreads();
    }
    __shared__ float rinv;
    if (c == 0) rinv = rsqrtf(fmaxf(sh[0], 1e-12f));
    __syncthreads();
    g_xnorm[b * CC + c] = m * rinv;
}

// ---------------------------------------------------------------------------
// Kernel 2: prompt_norm = l2_normalize(prompt_key, axis=1)
// ---------------------------------------------------------------------------
__global__ void key_norm_kernel(const float* __restrict__ pk) {
    int p = blockIdx.x;
    int c = threadIdx.x;
    float v = pk[(size_t)p * CC + c];

    __shared__ float sh[CC];
    sh[c] = v * v;
    __syncthreads();
    if (c < 256) sh[c] += sh[c + 256] + sh[c + 512];
    __syncthreads();
    for (int off = 128; off > 0; off >>= 1) {
        if (c < off) sh[c] += sh[c + off];
        __syncthreads();
    }
    __shared__ float rinv;
    if (c == 0) rinv = rsqrtf(fmaxf(sh[0], 1e-12f));
    __syncthreads();
    g_pnorm[p * CC + c] = v * rinv;
}

// ---------------------------------------------------------------------------
// Proj GEMM (tensor cores, tf32 mma.sync m16n8k8):
//   C[m,n] = sum_k A[m,k]*W[n,k]  + bias[n] + A[m,n]
//   M=8192, N=768, K=768.  BM=128, BN=64, BK=32.
//   256 threads = 8 warps in 4(m) x 2(n); warp tile 32x32.
// ---------------------------------------------------------------------------
#define LDA_S 36   // padded smem stride (floats)

__global__ __launch_bounds__(256)
void proj_mma_kernel(const float* __restrict__ A, const float* __restrict__ W,
                     const float* __restrict__ bias, float* __restrict__ Cm) {
    __shared__ uint32_t As[128 * LDA_S];
    __shared__ uint32_t Bs[64 * LDA_S];

    const int tid = threadIdx.x;
    const int lane = tid & 31;
    const int w = tid >> 5;
    const int wm = w >> 1;        // 0..3
    const int wn = w & 1;         // 0..1
    const int g  = lane >> 2;     // group id 0..7
    const int t  = lane & 3;      // 0..3

    const int m0 = blockIdx.y * 128;
    const int n0 = blockIdx.x * 64;

    // global load mapping: A: 4 float4/thread, B: 2 float4/thread
    const int f4c = (tid & 7) * 4;      // 0,4,...,28
    const int arow = tid >> 3;          // 0..31 (stride 32, x4)
    // prefetch regs
    float4 pa[4], pb[2];

    const float* Ag = A + (size_t)(m0 + arow) * CC + f4c;
    const float* Wg = W + (size_t)(n0 + arow) * CC + f4c;

    float acc[2][4][4];
    #pragma unroll
    for (int i = 0; i < 2; i++)
        #pragma unroll
        for (int j = 0; j < 4; j++)
            #pragma unroll
            for (int q = 0; q < 4; q++) acc[i][j][q] = 0.0f;

    // initial prefetch (k0 = 0)
    #pragma unroll
    for (int r = 0; r < 4; r++) pa[r] = *(const float4*)(Ag + (size_t)(r * 32) * CC);
    #pragma unroll
    for (int r = 0; r < 2; r++) pb[r] = *(const float4*)(Wg + (size_t)(r * 32) * CC);

    for (int kb = 0; kb < CC / 32; kb++) {
        __syncthreads();
        // store prefetched tile to smem (tf32-rounded)
        #pragma unroll
        for (int r = 0; r < 4; r++) {
            uint32_t* d = &As[(arow + r * 32) * LDA_S + f4c];
            d[0] = f2tf32(pa[r].x); d[1] = f2tf32(pa[r].y);
            d[2] = f2tf32(pa[r].z); d[3] = f2tf32(pa[r].w);
        }
        #pragma unroll
        for (int r = 0; r < 2; r++) {
            uint32_t* d = &Bs[(arow + r * 32) * LDA_S + f4c];
            d[0] = f2tf32(pb[r].x); d[1] = f2tf32(pb[r].y);
            d[2] = f2tf32(pb[r].z); d[3] = f2tf32(pb[r].w);
        }
        __syncthreads();

        // prefetch next k-block
        if (kb + 1 < CC / 32) {
            const float* Agn = Ag + (kb + 1) * 32;
            const float* Wgn = Wg + (kb + 1) * 32;
            #pragma unroll
            for (int r = 0; r < 4; r++) pa[r] = *(const float4*)(Agn + (size_t)(r * 32) * CC);
            #pragma unroll
            for (int r = 0; r < 2; r++) pb[r] = *(const float4*)(Wgn + (size_t)(r * 32) * CC);
        }

        // compute: 4 k-steps of 8
        #pragma unroll
        for (int ks = 0; ks < 4; ks++) {
            int kc = ks * 8;
            uint32_t af[2][4], bf[4][2];
            #pragma unroll
            for (int mi = 0; mi < 2; mi++) {
                int mb = wm * 32 + mi * 16;
                af[mi][0] = As[(mb + g)     * LDA_S + kc + t];
                af[mi][1] = As[(mb + g + 8) * LDA_S + kc + t];
                af[mi][2] = As[(mb + g)     * LDA_S + kc + t + 4];
                af[mi][3] = As[(mb + g + 8) * LDA_S + kc + t + 4];
            }
            #pragma unroll
            for (int ni = 0; ni < 4; ni++) {
                int nb = wn * 32 + ni * 8;
                bf[ni][0] = Bs[(nb + g) * LDA_S + kc + t];
                bf[ni][1] = Bs[(nb + g) * LDA_S + kc + t + 4];
            }
            #pragma unroll
            for (int mi = 0; mi < 2; mi++)
                #pragma unroll
                for (int ni = 0; ni < 4; ni++) {
                    asm volatile(
                        "mma.sync.aligned.m16n8k8.row.col.f32.tf32.tf32.f32 "
                        "{%0,%1,%2,%3}, {%4,%5,%6,%7}, {%8,%9}, {%0,%1,%2,%3};"
                        : "+f"(acc[mi][ni][0]), "+f"(acc[mi][ni][1]),
                          "+f"(acc[mi][ni][2]), "+f"(acc[mi][ni][3])
                        : "r"(af[mi][0]), "r"(af[mi][1]), "r"(af[mi][2]), "r"(af[mi][3]),
                          "r"(bf[ni][0]), "r"(bf[ni][1]));
                }
        }
    }

    // epilogue: + bias[n] + A[m][n]  (residual, N==K==CC)
    #pragma unroll
    for (int mi = 0; mi < 2; mi++) {
        int r0 = m0 + wm * 32 + mi * 16 + g;
        #pragma unroll
        for (int ni = 0; ni < 4; ni++) {
            int cc = n0 + wn * 32 + ni * 8 + t * 2;
            {
                float2 res = *(const float2*)(A + (size_t)r0 * CC + cc);
                float2 bs  = *(const float2*)(bias + cc);
                float2 v;
                v.x = acc[mi][ni][0] + bs.x + res.x;
                v.y = acc[mi][ni][1] + bs.y + res.y;
                *(float2*)(Cm + (size_t)r0 * CC + cc) = v;
            }
            {
                int r1 = r0 + 8;
                float2 res = *(const float2*)(A + (size_t)r1 * CC + cc);
                float2 bs  = *(const float2*)(bias + cc);
                float2 v;
                v.x = acc[mi][ni][2] + bs.x + res.x;
                v.y = acc[mi][ni][3] + bs.y + res.y;
                *(float2*)(Cm + (size_t)r1 * CC + cc) = v;
            }
        }
    }
}

// ---------------------------------------------------------------------------
// Sim GEMM (fp32 SIMT, exact): C[m,n] = sum_k A[m,k]*B[n,k]
// BM=BN=32, BK=32, TM=TN=2, 256 threads, grid 256 blocks (full chip).
// ---------------------------------------------------------------------------
__global__ __launch_bounds__(256)
void sim_gemm_kernel(const float* __restrict__ A, const float* __restrict__ Bm,
                     float* __restrict__ Cm) {
    __shared__ float As[32][33];
    __shared__ float Bs[32][33];

    const int tid = threadIdx.x;
    const int tx = tid & 15;   // n
    const int ty = tid >> 4;   // m
    const int m0 = blockIdx.y * 32;
    const int n0 = blockIdx.x * 32;

    const int lrow = tid >> 3;        // 0..31
    const int lk   = (tid & 7) * 4;

    float acc[2][2] = {{0.f,0.f},{0.f,0.f}};

    for (int k0 = 0; k0 < CC; k0 += 32) {
        float4 av = *(const float4*)(A  + (size_t)(m0 + lrow) * CC + k0 + lk);
        float4 bv = *(const float4*)(Bm + (size_t)(n0 + lrow) * CC + k0 + lk);
        __syncthreads();
        As[lrow][lk+0]=av.x; As[lrow][lk+1]=av.y; As[lrow][lk+2]=av.z; As[lrow][lk+3]=av.w;
        Bs[lrow][lk+0]=bv.x; Bs[lrow][lk+1]=bv.y; Bs[lrow][lk+2]=bv.z; Bs[lrow][lk+3]=bv.w;
        __syncthreads();
        #pragma unroll
        for (int kk = 0; kk < 32; kk++) {
            float a0 = As[ty*2+0][kk], a1 = As[ty*2+1][kk];
            float b0 = Bs[tx*2+0][kk], b1 = Bs[tx*2+1][kk];
            acc[0][0] = fmaf(a0,b0,acc[0][0]);
            acc[0][1] = fmaf(a0,b1,acc[0][1]);
            acc[1][0] = fmaf(a1,b0,acc[1][0]);
            acc[1][1] = fmaf(a1,b1,acc[1][1]);
        }
    }
    #pragma unroll
    for (int i = 0; i < 2; i++)
        #pragma unroll
        for (int j = 0; j < 2; j++)
            Cm[(size_t)(m0 + ty*2 + i) * POOL + n0 + tx*2 + j] = acc[i][j];
}

// Shared-memory As uses [32][33] but loads wrote via scalar; k index within
// row: note As[row][k] layout above (row-major by m), reads As[m][kk] — OK.

// ---------------------------------------------------------------------------
// per-batch top-8 (descending, ties -> smaller index) + value sum
// ---------------------------------------------------------------------------
__global__ void topk_kernel() {
    int b = blockIdx.x;
    int t = threadIdx.x;
    __shared__ float vals[POOL];
    __shared__ float rv[256];
    __shared__ int   ri[256];

    for (int p = t; p < POOL; p += 256) vals[p] = g_sim[b * POOL + p];
    __syncthreads();

    float tsum = 0.0f;
    for (int it = 0; it < KSEL; it++) {
        float bvv = -1e30f; int bii = 0x7fffffff;
        for (int p = t; p < POOL; p += 256) {
            float v = vals[p];
            if (v > bvv || (v == bvv && p < bii)) { bvv = v; bii = p; }
        }
        rv[t] = bvv; ri[t] = bii;
        __syncthreads();
        for (int off = 128; off > 0; off >>= 1) {
            if (t < off) {
                float v2 = rv[t + off]; int i2 = ri[t + off];
                if (v2 > rv[t] || (v2 == rv[t] && i2 < ri[t])) { rv[t] = v2; ri[t] = i2; }
            }
            __syncthreads();
        }
        if (t == 0) {
            g_idx[b * KSEL + it] = ri[0];
            tsum += rv[0];
            vals[ri[0]] = -1e30f;
        }
        __syncthreads();
    }
    if (t == 0) g_topsum[b] = tsum;
}

// ---------------------------------------------------------------------------
__global__ void reduce_sim_kernel(float* __restrict__ out) {
    __shared__ float sh[256];
    int t = threadIdx.x;
    sh[t] = g_topsum[t];
    __syncthreads();
    for (int off = 128; off > 0; off >>= 1) {
        if (t < off) sh[t] += sh[t + off];
        __syncthreads();
    }
    if (t == 0) out[PROMPTED_ELEMS] = sh[0] / (float)BB;
}

// ---------------------------------------------------------------------------
// assemble: [cls | gathered projected prompts | rest]
// ---------------------------------------------------------------------------
__global__ void assemble_kernel(const float* __restrict__ x, float* __restrict__ out) {
    int r = blockIdx.x;
    int b = blockIdx.y;
    int t = threadIdx.x;

    const float4* src;
    if (r == 0) {
        src = (const float4*)(x + (size_t)b * NTOK * CC);
    } else if (r <= KSEL * PLEN) {
        int j = r - 1;
        int k = j >> 3, l = j & 7;
        int pid = g_idx[b * KSEL + k];
        src = (const float4*)(g_proj + ((size_t)pid * PLEN + l) * CC);
    } else {
        src = (const float4*)(x + ((size_t)b * NTOK + (r - KSEL * PLEN)) * CC);
    }
    float4 v = src[t];
    ((float4*)(out + ((size_t)b * OUTROWS + r) * CC))[t] = v;
}

// ---------------------------------------------------------------------------
extern "C" void kernel_launch(void* const* d_in, const int* in_sizes, int n_in,
                              void* d_out, int out_size) {
    const float* x_embed = (const float*)d_in[0];
    const float* prompt  = (const float*)d_in[1];
    const float* pkey    = (const float*)d_in[2];
    const float* proj_w  = (const float*)d_in[3];
    const float* proj_b  = (const float*)d_in[4];
    float* out = (float*)d_out;

    float *p_xnorm, *p_pnorm, *p_sim, *p_proj;
    cudaGetSymbolAddress((void**)&p_xnorm, g_xnorm);
    cudaGetSymbolAddress((void**)&p_pnorm, g_pnorm);
    cudaGetSymbolAddress((void**)&p_sim,   g_sim);
    cudaGetSymbolAddress((void**)&p_proj,  g_proj);

    // 1) project ALL prompt rows (tf32 tensor cores): g_proj = prompt@W^T + b + prompt
    {
        dim3 grid(CC / 64, (POOL * PLEN) / 128);
        proj_mma_kernel<<<grid, 256>>>(prompt, proj_w, proj_b, p_proj);
    }

    // 2) normalized mean embedding + normalized keys
    mean_norm_kernel<<<BB, CC>>>(x_embed);
    key_norm_kernel<<<POOL, CC>>>(pkey);

    // 3) similarity = x_norm @ prompt_norm^T  [256, 1024] (exact fp32)
    {
        dim3 grid(POOL / 32, BB / 32);
        sim_gemm_kernel<<<grid, 256>>>(p_xnorm, p_pnorm, p_sim);
    }

    // 4) top-8 per batch
    topk_kernel<<<BB, 256>>>();

    // 5) reduce_sim scalar
    reduce_sim_kernel<<<1, 256>>>(out);

    // 6) assemble prompted output
    {
        dim3 grid(OUTROWS, BB);
        assemble_kernel<<<grid, 192>>>(x_embed, out);
    }
}

// round 4
// speedup vs baseline: 1.8697x; 1.0086x over previous
#include <cuda_runtime.h>
#include <math.h>
#include <stdint.h>

// Problem constants
#define BB      256
#define NTOK    197
#define CC      768
#define POOL    1024
#define PLEN    8
#define KSEL    8
#define OUTROWS 261
#define PROMPTED_ELEMS ((size_t)BB * OUTROWS * CC)

#define PROJ_M  (POOL * PLEN)   // 8192
#define NCHUNK  8               // token chunks for fused copy+mean

// Proj GEMM config
#define PBM 128
#define PBN 128
#define PBK 32                  // K floats per kblock
#define PNKB (CC / PBK)         // 24
#define PSTRIDE 36              // padded smem row stride (floats)
#define PSTAGE_FLOATS ((PBM + PBN) * PSTRIDE)   // 9216 floats / stage
#define PSTAGES 3
#define PROJ_SMEM (PSTAGES * PSTAGE_FLOATS * 4) // 110592 B

// Scratch (device globals)
__device__ float g_xnorm[BB * CC];
__device__ float g_pnorm[POOL * CC];
__device__ float g_sim[BB * POOL];
__device__ float g_proj[PROJ_M * CC];
__device__ float g_ar[PROJ_M * CC];     // tf32-rounded prompt
__device__ float g_wr[CC * CC];         // tf32-rounded weights
__device__ float g_msum[BB * NCHUNK * CC];
__device__ int   g_idx[BB * KSEL];
__device__ float g_topsum[BB];

// ---------------------------------------------------------------------------
__device__ __forceinline__ uint32_t f2tf32(float f) {
    uint32_t r;
    asm("cvt.rna.tf32.f32 %0, %1;" : "=r"(r) : "f"(f));
    return r;
}
__device__ __forceinline__ uint32_t smem_u32(const void* p) {
    uint32_t a;
    asm("{ .reg .u64 t; cvta.to.shared.u64 t, %1; cvt.u32.u64 %0, t; }"
        : "=r"(a) : "l"(p));
    return a;
}

// ---------------------------------------------------------------------------
// Elementwise tf32-rounding pass (rna): out[i] = tf32(in[i]) as fp32 bits
// ---------------------------------------------------------------------------
__global__ void round_tf32_kernel(const float* __restrict__ in,
                                  float* __restrict__ outp, int n4) {
    int i = blockIdx.x * blockDim.x + threadIdx.x;
    if (i < n4) {
        float4 v = ((const float4*)in)[i];
        v.x = __uint_as_float(f2tf32(v.x));
        v.y = __uint_as_float(f2tf32(v.y));
        v.z = __uint_as_float(f2tf32(v.z));
        v.w = __uint_as_float(f2tf32(v.w));
        ((float4*)outp)[i] = v;
    }
}

// ---------------------------------------------------------------------------
// Proj GEMM (mma.sync tf32, cp.async 3-stage):
//   C[m,n] = sum_k Am[m,k]*Wm[n,k] + bias[n] + Ares[m,n]
//   M=8192, N=768, K=768. CTA 128x128, 8 warps 4(m) x 2(n), warp tile 32x64.
//   Inputs Am/Wm are pre-rounded to tf32 -> no CVT in hot loop.
// ---------------------------------------------------------------------------
__global__ __launch_bounds__(256)
void proj_tc_kernel(const float* __restrict__ Am, const float* __restrict__ Wm,
                    const float* __restrict__ Ares, const float* __restrict__ bias,
                    float* __restrict__ Cm) {
    extern __shared__ float sm[];

    const int tid  = threadIdx.x;
    const int lane = tid & 31;
    const int wid  = tid >> 5;
    const int wm   = wid >> 1;   // 0..3
    const int wn   = wid & 1;    // 0..1
    const int g    = lane >> 2;  // 0..7
    const int t    = lane & 3;   // 0..3
    const int m0   = blockIdx.y * PBM;
    const int n0   = blockIdx.x * PBN;

    // cp.async mapping: thread -> row (tid>>1), 4 chunks of 16B (half row)
    const int arow = tid >> 1;
    const int cb   = (tid & 1) * 4;
    const float* agp = Am + (size_t)(m0 + arow) * CC + cb * 4;
    const float* wgp = Wm + (size_t)(n0 + arow) * CC + cb * 4;
    const uint32_t smbase = smem_u32(sm);
    const uint32_t arow_off = (uint32_t)arow * (PSTRIDE * 4) + (uint32_t)cb * 16;

    float acc[2][8][4];
    #pragma unroll
    for (int mi = 0; mi < 2; mi++)
        #pragma unroll
        for (int ni = 0; ni < 8; ni++)
            #pragma unroll
            for (int q = 0; q < 4; q++) acc[mi][ni][q] = 0.0f;

    // stage issue helper
    auto issue = [&](int kb) {
        int s = kb % PSTAGES;
        uint32_t ab = smbase + (uint32_t)(s * PSTAGE_FLOATS) * 4 + arow_off;
        uint32_t bb = ab + (uint32_t)(PBM * PSTRIDE) * 4;
        const float* ag = agp + kb * PBK;
        const float* wg = wgp + kb * PBK;
        #pragma unroll
        for (int i = 0; i < 4; i++) {
            asm volatile("cp.async.cg.shared.global [%0], [%1], 16;"
                         :: "r"(ab + i * 16), "l"(ag + i * 4) : "memory");
            asm volatile("cp.async.cg.shared.global [%0], [%1], 16;"
                         :: "r"(bb + i * 16), "l"(wg + i * 4) : "memory");
        }
        asm volatile("cp.async.commit_group;" ::: "memory");
    };

    // prologue: stages 0,1 in flight
    issue(0);
    issue(1);

    for (int kb = 0; kb < PNKB; kb++) {
        // ensure stage kb arrived (own copies), then block-wide visibility
        if (kb + 1 < PNKB) {
            asm volatile("cp.async.wait_group 1;" ::: "memory");
        } else {
            asm volatile("cp.async.wait_group 0;" ::: "memory");
        }
        __syncthreads();   // also guards buffer reuse vs previous compute

        if (kb + 2 < PNKB) issue(kb + 2);

        const float* As = sm + (kb % PSTAGES) * PSTAGE_FLOATS;
        const float* Bs = As + PBM * PSTRIDE;

        #pragma unroll
        for (int ks = 0; ks < 4; ks++) {
            const int kc = ks * 8;
            uint32_t af[2][4];
            #pragma unroll
            for (int mi = 0; mi < 2; mi++) {
                int row = wm * 32 + mi * 16;
                af[mi][0] = __float_as_uint(As[(row + g)     * PSTRIDE + kc + t]);
                af[mi][1] = __float_as_uint(As[(row + g + 8) * PSTRIDE + kc + t]);
                af[mi][2] = __float_as_uint(As[(row + g)     * PSTRIDE + kc + t + 4]);
                af[mi][3] = __float_as_uint(As[(row + g + 8) * PSTRIDE + kc + t + 4]);
            }
            uint32_t bf[8][2];
            #pragma unroll
            for (int ni = 0; ni < 8; ni++) {
                int col = wn * 64 + ni * 8;
                bf[ni][0] = __float_as_uint(Bs[(col + g) * PSTRIDE + kc + t]);
                bf[ni][1] = __float_as_uint(Bs[(col + g) * PSTRIDE + kc + t + 4]);
            }
            #pragma unroll
            for (int mi = 0; mi < 2; mi++)
                #pragma unroll
                for (int ni = 0; ni < 8; ni++) {
                    asm volatile(
                        "mma.sync.aligned.m16n8k8.row.col.f32.tf32.tf32.f32 "
                        "{%0,%1,%2,%3}, {%4,%5,%6,%7}, {%8,%9}, {%0,%1,%2,%3};"
                        : "+f"(acc[mi][ni][0]), "+f"(acc[mi][ni][1]),
                          "+f"(acc[mi][ni][2]), "+f"(acc[mi][ni][3])
                        : "r"(af[mi][0]), "r"(af[mi][1]), "r"(af[mi][2]), "r"(af[mi][3]),
                          "r"(bf[ni][0]), "r"(bf[ni][1]));
                }
        }
    }

    // epilogue: + bias[n] + Ares[m][n]
    #pragma unroll
    for (int mi = 0; mi < 2; mi++) {
        int r0 = m0 + wm * 32 + mi * 16 + g;
        int r1 = r0 + 8;
        #pragma unroll
        for (int ni = 0; ni < 8; ni++) {
            int n = n0 + wn * 64 + ni * 8 + t * 2;
            {
                float2 res = *(const float2*)(Ares + (size_t)r0 * CC + n);
                float2 bs  = *(const float2*)(bias + n);
                float2 v;
                v.x = acc[mi][ni][0] + bs.x + res.x;
                v.y = acc[mi][ni][1] + bs.y + res.y;
                *(float2*)(Cm + (size_t)r0 * CC + n) = v;
            }
            {
                float2 res = *(const float2*)(Ares + (size_t)r1 * CC + n);
                float2 bs  = *(const float2*)(bias + n);
                float2 v;
                v.x = acc[mi][ni][2] + bs.x + res.x;
                v.y = acc[mi][ni][3] + bs.y + res.y;
                *(float2*)(Cm + (size_t)r1 * CC + n) = v;
            }
        }
    }
}

// ---------------------------------------------------------------------------
// Fused copy + partial mean: copies the idx-independent rows of the output
// (cls + tokens 1..196) AND accumulates per-chunk token sums for the mean.
// grid (NCHUNK, BB), 192 threads (x float4 = 768 floats/row)
// ---------------------------------------------------------------------------
__global__ void copy_mean_kernel(const float* __restrict__ x, float* __restrict__ out) {
    const int ch = blockIdx.x;
    const int b  = blockIdx.y;
    const int t  = threadIdx.x;

    const int t0 = ch * 25;
    const int t1 = (t0 + 25 < NTOK) ? t0 + 25 : NTOK;

    float4 acc = make_float4(0.f, 0.f, 0.f, 0.f);
    const float4* xb = (const float4*)(x + (size_t)b * NTOK * CC);
    float4* ob = (float4*)(out + (size_t)b * OUTROWS * CC);

    for (int tok = t0; tok < t1; tok++) {
        float4 v = xb[(size_t)tok * (CC / 4) + t];
        acc.x += v.x; acc.y += v.y; acc.z += v.z; acc.w += v.w;
        int orow = (tok == 0) ? 0 : tok + KSEL * PLEN;
        ob[(size_t)orow * (CC / 4) + t] = v;
    }
    ((float4*)g_msum)[((size_t)b * NCHUNK + ch) * (CC / 4) + t] = acc;
}

// ---------------------------------------------------------------------------
// Finish mean: sum chunks, /197, L2-normalize -> g_xnorm. One block per batch.
// ---------------------------------------------------------------------------
__global__ void mean_finish_kernel() {
    int b = blockIdx.x;
    int c = threadIdx.x;
    float s = 0.0f;
    #pragma unroll
    for (int ch = 0; ch < NCHUNK; ch++)
        s += g_msum[((size_t)b * NCHUNK + ch) * CC + c];
    float m = s / (float)NTOK;

    __shared__ float sh[CC];
    sh[c] = m * m;
    __syncthreads();
    if (c < 256) sh[c] += sh[c + 256] + sh[c + 512];
    __syncthreads();
    for (int off = 128; off > 0; off >>= 1) {
        if (c < off) sh[c] += sh[c + off];
        __syncthreads();
    }
    __shared__ float rinv;
    if (c == 0) rinv = rsqrtf(fmaxf(sh[0], 1e-12f));
    __syncthreads();
    g_xnorm[b * CC + c] = m * rinv;
}

// ---------------------------------------------------------------------------
__global__ void key_norm_kernel(const float* __restrict__ pk) {
    int p = blockIdx.x;
    int c = threadIdx.x;
    float v = pk[(size_t)p * CC + c];

    __shared__ float sh[CC];
    sh[c] = v * v;
    __syncthreads();
    if (c < 256) sh[c] += sh[c + 256] + sh[c + 512];
    __syncthreads();
    for (int off = 128; off > 0; off >>= 1) {
        if (c < off) sh[c] += sh[c + off];
        __syncthreads();
    }
    __shared__ float rinv;
    if (c == 0) rinv = rsqrtf(fmaxf(sh[0], 1e-12f));
    __syncthreads();
    g_pnorm[p * CC + c] = v * rinv;
}

// ---------------------------------------------------------------------------
// Sim GEMM (fp32 SIMT, exact): C[m,n] = sum_k A[m,k]*B[n,k]
// ---------------------------------------------------------------------------
__global__ __launch_bounds__(256)
void sim_gemm_kernel(const float* __restrict__ A, const float* __restrict__ Bm,
                     float* __restrict__ Cm) {
    __shared__ float As[32][33];
    __shared__ float Bs[32][33];

    const int tid = threadIdx.x;
    const int tx = tid & 15;
    const int ty = tid >> 4;
    const int m0 = blockIdx.y * 32;
    const int n0 = blockIdx.x * 32;

    const int lrow = tid >> 3;
    const int lk   = (tid & 7) * 4;

    float acc[2][2] = {{0.f,0.f},{0.f,0.f}};

    for (int k0 = 0; k0 < CC; k0 += 32) {
        float4 av = *(const float4*)(A  + (size_t)(m0 + lrow) * CC + k0 + lk);
        float4 bv = *(const float4*)(Bm + (size_t)(n0 + lrow) * CC + k0 + lk);
        __syncthreads();
        As[lrow][lk+0]=av.x; As[lrow][lk+1]=av.y; As[lrow][lk+2]=av.z; As[lrow][lk+3]=av.w;
        Bs[lrow][lk+0]=bv.x; Bs[lrow][lk+1]=bv.y; Bs[lrow][lk+2]=bv.z; Bs[lrow][lk+3]=bv.w;
        __syncthreads();
        #pragma unroll
        for (int kk = 0; kk < 32; kk++) {
            float a0 = As[ty*2+0][kk], a1 = As[ty*2+1][kk];
            float b0 = Bs[tx*2+0][kk], b1 = Bs[tx*2+1][kk];
            acc[0][0] = fmaf(a0,b0,acc[0][0]);
            acc[0][1] = fmaf(a0,b1,acc[0][1]);
            acc[1][0] = fmaf(a1,b0,acc[1][0]);
            acc[1][1] = fmaf(a1,b1,acc[1][1]);
        }
    }
    #pragma unroll
    for (int i = 0; i < 2; i++)
        #pragma unroll
        for (int j = 0; j < 2; j++)
            Cm[(size_t)(m0 + ty*2 + i) * POOL + n0 + tx*2 + j] = acc[i][j];
}

// ---------------------------------------------------------------------------
__global__ void topk_kernel() {
    int b = blockIdx.x;
    int t = threadIdx.x;
    __shared__ float vals[POOL];
    __shared__ float rv[256];
    __shared__ int   ri[256];

    for (int p = t; p < POOL; p += 256) vals[p] = g_sim[b * POOL + p];
    __syncthreads();

    float tsum = 0.0f;
    for (int it = 0; it < KSEL; it++) {
        float bvv = -1e30f; int bii = 0x7fffffff;
        for (int p = t; p < POOL; p += 256) {
            float v = vals[p];
            if (v > bvv || (v == bvv && p < bii)) { bvv = v; bii = p; }
        }
        rv[t] = bvv; ri[t] = bii;
        __syncthreads();
        for (int off = 128; off > 0; off >>= 1) {
            if (t < off) {
                float v2 = rv[t + off]; int i2 = ri[t + off];
                if (v2 > rv[t] || (v2 == rv[t] && i2 < ri[t])) { rv[t] = v2; ri[t] = i2; }
            }
            __syncthreads();
        }
        if (t == 0) {
            g_idx[b * KSEL + it] = ri[0];
            tsum += rv[0];
            vals[ri[0]] = -1e30f;
        }
        __syncthreads();
    }
    if (t == 0) g_topsum[b] = tsum;
}

// ---------------------------------------------------------------------------
__global__ void reduce_sim_kernel(float* __restrict__ out) {
    __shared__ float sh[256];
    int t = threadIdx.x;
    sh[t] = g_topsum[t];
    __syncthreads();
    for (int off = 128; off > 0; off >>= 1) {
        if (t < off) sh[t] += sh[t + off];
        __syncthreads();
    }
    if (t == 0) out[PROMPTED_ELEMS] = sh[0] / (float)BB;
}

// ---------------------------------------------------------------------------
// Gather: out rows 1..64 = projected prompts selected by idx
// ---------------------------------------------------------------------------
__global__ void gather_kernel(float* __restrict__ out) {
    int j = blockIdx.x;   // 0..63
    int b = blockIdx.y;
    int t = threadIdx.x;  // 0..191

    int pid = g_idx[b * KSEL + (j >> 3)];
    const float4* src = (const float4*)(g_proj + ((size_t)pid * PLEN + (j & 7)) * CC);
    float4 v = src[t];
    ((float4*)(out + ((size_t)b * OUTROWS + 1 + j) * CC))[t] = v;
}

// ---------------------------------------------------------------------------
extern "C" void kernel_launch(void* const* d_in, const int* in_sizes, int n_in,
                              void* d_out, int out_size) {
    const float* x_embed = (const float*)d_in[0];
    const float* prompt  = (const float*)d_in[1];
    const float* pkey    = (const float*)d_in[2];
    const float* proj_w  = (const float*)d_in[3];
    const float* proj_b  = (const float*)d_in[4];
    float* out = (float*)d_out;

    float *p_xnorm, *p_pnorm, *p_sim, *p_proj, *p_ar, *p_wr;
    cudaGetSymbolAddress((void**)&p_xnorm, g_xnorm);
    cudaGetSymbolAddress((void**)&p_pnorm, g_pnorm);
    cudaGetSymbolAddress((void**)&p_sim,   g_sim);
    cudaGetSymbolAddress((void**)&p_proj,  g_proj);
    cudaGetSymbolAddress((void**)&p_ar,    g_ar);
    cudaGetSymbolAddress((void**)&p_wr,    g_wr);

    // 0) pre-round prompt & W to tf32 (rna) -> hot GEMM loop needs no CVT
    {
        int n4a = PROJ_M * CC / 4;
        round_tf32_kernel<<<(n4a + 255) / 256, 256>>>(prompt, p_ar, n4a);
        int n4w = CC * CC / 4;
        round_tf32_kernel<<<(n4w + 255) / 256, 256>>>(proj_w, p_wr, n4w);
    }

    // 1) proj GEMM: g_proj = prompt@W^T + b + prompt  (tf32 mma.sync + cp.async)
    {
        cudaFuncSetAttribute(proj_tc_kernel,
                             cudaFuncAttributeMaxDynamicSharedMemorySize, PROJ_SMEM);
        dim3 grid(CC / PBN, PROJ_M / PBM);   // (6, 64) = 384 CTAs
        proj_tc_kernel<<<grid, 256, PROJ_SMEM>>>(p_ar, p_wr, prompt, proj_b, p_proj);
    }

    // 2) fused copy (idx-independent output rows) + partial mean sums
    {
        dim3 grid(NCHUNK, BB);
        copy_mean_kernel<<<grid, 192>>>(x_embed, out);
    }
    mean_finish_kernel<<<BB, CC>>>();
    key_norm_kernel<<<POOL, CC>>>(pkey);

    // 3) similarity (exact fp32)
    {
        dim3 grid(POOL / 32, BB / 32);
        sim_gemm_kernel<<<grid, 256>>>(p_xnorm, p_pnorm, p_sim);
    }

    // 4) top-8 + reduce_sim
    topk_kernel<<<BB, 256>>>();
    reduce_sim_kernel<<<1, 256>>>(out);

    // 5) gather selected projected prompts into output rows 1..64
    {
        dim3 grid(KSEL * PLEN, BB);
        gather_kernel<<<grid, 192>>>(out);
    }
}

// round 5
// speedup vs baseline: 2.6891x; 1.4383x over previous
#include <cuda_runtime.h>
#include <cuda_fp16.h>
#include <math.h>
#include <stdint.h>

// Problem constants
#define BB      256
#define NTOK    197
#define CC      768
#define POOL    1024
#define PLEN    8
#define KSEL    8
#define OUTROWS 261
#define PROMPTED_ELEMS ((size_t)BB * OUTROWS * CC)

#define PROJ_M  (POOL * PLEN)   // 8192
#define NCHUNK  8

// Proj GEMM config (fp16 mma.m16n8k16 + ldmatrix)
#define PBM 128
#define PBN 128
#define PBKH 64                       // halves per kblock (128B rows)
#define PNKB (CC / PBKH)              // 12
#define STAGE_BYTES (256 * 128)       // A(128 rows)+B(128 rows) x 128B = 32KB
#define PSTAGES 3
#define PROJ_SMEM (PSTAGES * STAGE_BYTES)   // 98304 B

// Scratch (device globals)
__device__ float  g_xnorm[BB * CC];
__device__ float  g_pnorm[POOL * CC];
__device__ float  g_sim[BB * POOL];
__device__ float  g_proj[PROJ_M * CC];
__device__ __half g_ah[PROJ_M * CC];   // fp16 prompt
__device__ __half g_wh[CC * CC];       // fp16 weights
__device__ float  g_msum[BB * NCHUNK * CC];
__device__ int    g_idx[BB * KSEL];
__device__ float  g_topsum[BB];

// ---------------------------------------------------------------------------
__device__ __forceinline__ uint32_t smem_u32(const void* p) {
    uint32_t a;
    asm("{ .reg .u64 t; cvta.to.shared.u64 t, %1; cvt.u32.u64 %0, t; }"
        : "=r"(a) : "l"(p));
    return a;
}

// ---------------------------------------------------------------------------
// fp32 -> fp16 conversion (rn), 8 elems/thread
// ---------------------------------------------------------------------------
__global__ void f32_to_f16_kernel(const float* __restrict__ in,
                                  __half* __restrict__ outp, int n8) {
    int i = blockIdx.x * blockDim.x + threadIdx.x;
    if (i < n8) {
        const float4* p = (const float4*)in + (size_t)i * 2;
        float4 a = p[0], b = p[1];
        __half2 h[4];
        h[0] = __floats2half2_rn(a.x, a.y);
        h[1] = __floats2half2_rn(a.z, a.w);
        h[2] = __floats2half2_rn(b.x, b.y);
        h[3] = __floats2half2_rn(b.z, b.w);
        *(uint4*)((char*)outp + (size_t)i * 16) = *(uint4*)h;
    }
}

// ---------------------------------------------------------------------------
// Proj GEMM (fp16 mma + ldmatrix + cp.async 3-stage):
//   C[m,n] = sum_k Ah[m,k]*Wh[n,k] + bias[n] + Ares[m,n]
//   CTA 128x128, 8 warps 4(m) x 2(n), warp tile 32x64.
//   Smem: per stage, A rows 0-127 then W rows 0-127, 128B/row, XOR-8 swizzle.
// ---------------------------------------------------------------------------
__global__ __launch_bounds__(256)
void proj_fp16_kernel(const __half* __restrict__ Ah, const __half* __restrict__ Wh,
                      const float* __restrict__ Ares, const float* __restrict__ bias,
                      float* __restrict__ Cm) {
    extern __shared__ char sm[];
    const uint32_t smbase = smem_u32(sm);

    const int tid  = threadIdx.x;
    const int lane = tid & 31;
    const int wid  = tid >> 5;
    const int wm   = wid >> 1;    // 0..3
    const int wn   = wid & 1;     // 0..1
    const int m0   = blockIdx.y * PBM;
    const int n0   = blockIdx.x * PBN;

    // cp.async mapping: 8 threads/row, rows r = (tid>>3) + 32*i, chunk c = tid&7
    const int crow = tid >> 3;    // 0..31
    const int cch  = tid & 7;

    float acc[2][8][4];
    #pragma unroll
    for (int mi = 0; mi < 2; mi++)
        #pragma unroll
        for (int nt = 0; nt < 8; nt++)
            #pragma unroll
            for (int q = 0; q < 4; q++) acc[mi][nt][q] = 0.0f;

    auto issue = [&](int kb) {
        uint32_t stage = smbase + (uint32_t)((kb % PSTAGES) * STAGE_BYTES);
        #pragma unroll
        for (int i = 0; i < 8; i++) {
            int row = crow + i * 32;     // 0..255
            const __half* src = (row < 128)
                ? (Ah + (size_t)(m0 + row) * CC + kb * PBKH + cch * 8)
                : (Wh + (size_t)(n0 + row - 128) * CC + kb * PBKH + cch * 8);
            uint32_t dst = stage + (uint32_t)row * 128u
                         + (uint32_t)((cch ^ (row & 7)) << 4);
            asm volatile("cp.async.cg.shared.global [%0], [%1], 16;"
                         :: "r"(dst), "l"(src) : "memory");
        }
        asm volatile("cp.async.commit_group;" ::: "memory");
    };

    issue(0);
    issue(1);

    const int q = lane >> 3;   // ldmatrix tile id 0..3
    const int r = lane & 7;

    for (int kb = 0; kb < PNKB; kb++) {
        if (kb + 1 < PNKB) {
            asm volatile("cp.async.wait_group 1;" ::: "memory");
        } else {
            asm volatile("cp.async.wait_group 0;" ::: "memory");
        }
        __syncthreads();
        if (kb + 2 < PNKB) issue(kb + 2);

        const uint32_t Ab = smbase + (uint32_t)((kb % PSTAGES) * STAGE_BYTES);
        const uint32_t Bb = Ab + 16384u;

        #pragma unroll
        for (int ks = 0; ks < 4; ks++) {
            const int cb = ks * 2 + (q >> 1);
            uint32_t a[2][4];
            #pragma unroll
            for (int mi = 0; mi < 2; mi++) {
                int row = wm * 32 + mi * 16 + (q & 1) * 8 + r;
                uint32_t addr = Ab + (uint32_t)row * 128u
                              + (uint32_t)((cb ^ (row & 7)) << 4);
                asm volatile("ldmatrix.sync.aligned.m8n8.x4.shared.b16 "
                             "{%0,%1,%2,%3}, [%4];"
                             : "=r"(a[mi][0]), "=r"(a[mi][1]),
                               "=r"(a[mi][2]), "=r"(a[mi][3])
                             : "r"(addr));
            }
            uint32_t b[8][2];
            #pragma unroll
            for (int nj = 0; nj < 4; nj++) {
                int row = wn * 64 + nj * 16 + (q & 1) * 8 + r;
                uint32_t addr = Bb + (uint32_t)row * 128u
                              + (uint32_t)((cb ^ (row & 7)) << 4);
                uint32_t r0, r1, r2, r3;
                asm volatile("ldmatrix.sync.aligned.m8n8.x4.shared.b16 "
                             "{%0,%1,%2,%3}, [%4];"
                             : "=r"(r0), "=r"(r1), "=r"(r2), "=r"(r3)
                             : "r"(addr));
                b[nj * 2 + 0][0] = r0; b[nj * 2 + 0][1] = r2;
                b[nj * 2 + 1][0] = r1; b[nj * 2 + 1][1] = r3;
            }
            #pragma unroll
            for (int mi = 0; mi < 2; mi++)
                #pragma unroll
                for (int nt = 0; nt < 8; nt++) {
                    asm volatile(
                        "mma.sync.aligned.m16n8k16.row.col.f32.f16.f16.f32 "
                        "{%0,%1,%2,%3}, {%4,%5,%6,%7}, {%8,%9}, {%0,%1,%2,%3};"
                        : "+f"(acc[mi][nt][0]), "+f"(acc[mi][nt][1]),
                          "+f"(acc[mi][nt][2]), "+f"(acc[mi][nt][3])
                        : "r"(a[mi][0]), "r"(a[mi][1]), "r"(a[mi][2]), "r"(a[mi][3]),
                          "r"(b[nt][0]), "r"(b[nt][1]));
                }
        }
    }

    // epilogue: + bias[n] + Ares[m][n]
    #pragma unroll
    for (int mi = 0; mi < 2; mi++) {
        int r0 = m0 + wm * 32 + mi * 16 + (lane >> 2);
        int r1 = r0 + 8;
        #pragma unroll
        for (int nt = 0; nt < 8; nt++) {
            int n = n0 + wn * 64 + nt * 8 + (lane & 3) * 2;
            {
                float2 res = *(const float2*)(Ares + (size_t)r0 * CC + n);
                float2 bs  = *(const float2*)(bias + n);
                float2 v;
                v.x = acc[mi][nt][0] + bs.x + res.x;
                v.y = acc[mi][nt][1] + bs.y + res.y;
                *(float2*)(Cm + (size_t)r0 * CC + n) = v;
            }
            {
                float2 res = *(const float2*)(Ares + (size_t)r1 * CC + n);
                float2 bs  = *(const float2*)(bias + n);
                float2 v;
                v.x = acc[mi][nt][2] + bs.x + res.x;
                v.y = acc[mi][nt][3] + bs.y + res.y;
                *(float2*)(Cm + (size_t)r1 * CC + n) = v;
            }
        }
    }
}

// ---------------------------------------------------------------------------
// Fused copy + partial mean (idx-independent output rows + chunk sums)
// ---------------------------------------------------------------------------
__global__ void copy_mean_kernel(const float* __restrict__ x, float* __restrict__ out) {
    const int ch = blockIdx.x;
    const int b  = blockIdx.y;
    const int t  = threadIdx.x;

    const int t0 = ch * 25;
    const int t1 = (t0 + 25 < NTOK) ? t0 + 25 : NTOK;

    float4 acc = make_float4(0.f, 0.f, 0.f, 0.f);
    const float4* xb = (const float4*)(x + (size_t)b * NTOK * CC);
    float4* ob = (float4*)(out + (size_t)b * OUTROWS * CC);

    for (int tok = t0; tok < t1; tok++) {
        float4 v = xb[(size_t)tok * (CC / 4) + t];
        acc.x += v.x; acc.y += v.y; acc.z += v.z; acc.w += v.w;
        int orow = (tok == 0) ? 0 : tok + KSEL * PLEN;
        ob[(size_t)orow * (CC / 4) + t] = v;
    }
    ((float4*)g_msum)[((size_t)b * NCHUNK + ch) * (CC / 4) + t] = acc;
}

// ---------------------------------------------------------------------------
__global__ void mean_finish_kernel() {
    int b = blockIdx.x;
    int c = threadIdx.x;
    float s = 0.0f;
    #pragma unroll
    for (int ch = 0; ch < NCHUNK; ch++)
        s += g_msum[((size_t)b * NCHUNK + ch) * CC + c];
    float m = s / (float)NTOK;

    __shared__ float sh[CC];
    sh[c] = m * m;
    __syncthreads();
    if (c < 256) sh[c] += sh[c + 256] + sh[c + 512];
    __syncthreads();
    for (int off = 128; off > 0; off >>= 1) {
        if (c < off) sh[c] += sh[c + off];
        __syncthreads();
    }
    __shared__ float rinv;
    if (c == 0) rinv = rsqrtf(fmaxf(sh[0], 1e-12f));
    __syncthreads();
    g_xnorm[b * CC + c] = m * rinv;
}

// ---------------------------------------------------------------------------
__global__ void key_norm_kernel(const float* __restrict__ pk) {
    int p = blockIdx.x;
    int c = threadIdx.x;
    float v = pk[(size_t)p * CC + c];

    __shared__ float sh[CC];
    sh[c] = v * v;
    __syncthreads();
    if (c < 256) sh[c] += sh[c + 256] + sh[c + 512];
    __syncthreads();
    for (int off = 128; off > 0; off >>= 1) {
        if (c < off) sh[c] += sh[c + off];
        __syncthreads();
    }
    __shared__ float rinv;
    if (c == 0) rinv = rsqrtf(fmaxf(sh[0], 1e-12f));
    __syncthreads();
    g_pnorm[p * CC + c] = v * rinv;
}

// ---------------------------------------------------------------------------
// Sim GEMM (fp32 SIMT, exact — feeds top-k, must stay fp32)
// ---------------------------------------------------------------------------
__global__ __launch_bounds__(256)
void sim_gemm_kernel(const float* __restrict__ A, const float* __restrict__ Bm,
                     float* __restrict__ Cm) {
    __shared__ float As[32][33];
    __shared__ float Bs[32][33];

    const int tid = threadIdx.x;
    const int tx = tid & 15;
    const int ty = tid >> 4;
    const int m0 = blockIdx.y * 32;
    const int n0 = blockIdx.x * 32;

    const int lrow = tid >> 3;
    const int lk   = (tid & 7) * 4;

    float acc[2][2] = {{0.f,0.f},{0.f,0.f}};

    for (int k0 = 0; k0 < CC; k0 += 32) {
        float4 av = *(const float4*)(A  + (size_t)(m0 + lrow) * CC + k0 + lk);
        float4 bv = *(const float4*)(Bm + (size_t)(n0 + lrow) * CC + k0 + lk);
        __syncthreads();
        As[lrow][lk+0]=av.x; As[lrow][lk+1]=av.y; As[lrow][lk+2]=av.z; As[lrow][lk+3]=av.w;
        Bs[lrow][lk+0]=bv.x; Bs[lrow][lk+1]=bv.y; Bs[lrow][lk+2]=bv.z; Bs[lrow][lk+3]=bv.w;
        __syncthreads();
        #pragma unroll
        for (int kk = 0; kk < 32; kk++) {
            float a0 = As[ty*2+0][kk], a1 = As[ty*2+1][kk];
            float b0 = Bs[tx*2+0][kk], b1 = Bs[tx*2+1][kk];
            acc[0][0] = fmaf(a0,b0,acc[0][0]);
            acc[0][1] = fmaf(a0,b1,acc[0][1]);
            acc[1][0] = fmaf(a1,b0,acc[1][0]);
            acc[1][1] = fmaf(a1,b1,acc[1][1]);
        }
    }
    #pragma unroll
    for (int i = 0; i < 2; i++)
        #pragma unroll
        for (int j = 0; j < 2; j++)
            Cm[(size_t)(m0 + ty*2 + i) * POOL + n0 + tx*2 + j] = acc[i][j];
}

// ---------------------------------------------------------------------------
__global__ void topk_kernel() {
    int b = blockIdx.x;
    int t = threadIdx.x;
    __shared__ float vals[POOL];
    __shared__ float rv[256];
    __shared__ int   ri[256];

    for (int p = t; p < POOL; p += 256) vals[p] = g_sim[b * POOL + p];
    __syncthreads();

    float tsum = 0.0f;
    for (int it = 0; it < KSEL; it++) {
        float bvv = -1e30f; int bii = 0x7fffffff;
        for (int p = t; p < POOL; p += 256) {
            float v = vals[p];
            if (v > bvv || (v == bvv && p < bii)) { bvv = v; bii = p; }
        }
        rv[t] = bvv; ri[t] = bii;
        __syncthreads();
        for (int off = 128; off > 0; off >>= 1) {
            if (t < off) {
                float v2 = rv[t + off]; int i2 = ri[t + off];
                if (v2 > rv[t] || (v2 == rv[t] && i2 < ri[t])) { rv[t] = v2; ri[t] = i2; }
            }
            __syncthreads();
        }
        if (t == 0) {
            g_idx[b * KSEL + it] = ri[0];
            tsum += rv[0];
            vals[ri[0]] = -1e30f;
        }
        __syncthreads();
    }
    if (t == 0) g_topsum[b] = tsum;
}

// ---------------------------------------------------------------------------
__global__ void reduce_sim_kernel(float* __restrict__ out) {
    __shared__ float sh[256];
    int t = threadIdx.x;
    sh[t] = g_topsum[t];
    __syncthreads();
    for (int off = 128; off > 0; off >>= 1) {
        if (t < off) sh[t] += sh[t + off];
        __syncthreads();
    }
    if (t == 0) out[PROMPTED_ELEMS] = sh[0] / (float)BB;
}

// ---------------------------------------------------------------------------
__global__ void gather_kernel(float* __restrict__ out) {
    int j = blockIdx.x;   // 0..63
    int b = blockIdx.y;
    int t = threadIdx.x;  // 0..191

    int pid = g_idx[b * KSEL + (j >> 3)];
    const float4* src = (const float4*)(g_proj + ((size_t)pid * PLEN + (j & 7)) * CC);
    float4 v = src[t];
    ((float4*)(out + ((size_t)b * OUTROWS + 1 + j) * CC))[t] = v;
}

// ---------------------------------------------------------------------------
extern "C" void kernel_launch(void* const* d_in, const int* in_sizes, int n_in,
                              void* d_out, int out_size) {
    const float* x_embed = (const float*)d_in[0];
    const float* prompt  = (const float*)d_in[1];
    const float* pkey    = (const float*)d_in[2];
    const float* proj_w  = (const float*)d_in[3];
    const float* proj_b  = (const float*)d_in[4];
    float* out = (float*)d_out;

    float *p_xnorm, *p_pnorm, *p_sim, *p_proj;
    __half *p_ah, *p_wh;
    cudaGetSymbolAddress((void**)&p_xnorm, g_xnorm);
    cudaGetSymbolAddress((void**)&p_pnorm, g_pnorm);
    cudaGetSymbolAddress((void**)&p_sim,   g_sim);
    cudaGetSymbolAddress((void**)&p_proj,  g_proj);
    cudaGetSymbolAddress((void**)&p_ah,    g_ah);
    cudaGetSymbolAddress((void**)&p_wh,    g_wh);

    // 1-2) convert prompt & W to fp16
    {
        int n8a = PROJ_M * CC / 8;
        f32_to_f16_kernel<<<(n8a + 255) / 256, 256>>>(prompt, p_ah, n8a);
        int n8w = CC * CC / 8;
        f32_to_f16_kernel<<<(n8w + 255) / 256, 256>>>(proj_w, p_wh, n8w);
    }

    // 3) fused copy + partial mean
    {
        dim3 grid(NCHUNK, BB);
        copy_mean_kernel<<<grid, 192>>>(x_embed, out);
    }

    // 4) proj GEMM (fp16 mma + ldmatrix) — 4th launch, ncu-captured
    {
        cudaFuncSetAttribute(proj_fp16_kernel,
                             cudaFuncAttributeMaxDynamicSharedMemorySize, PROJ_SMEM);
        dim3 grid(CC / PBN, PROJ_M / PBM);   // (6, 64)
        proj_fp16_kernel<<<grid, 256, PROJ_SMEM>>>(p_ah, p_wh, prompt, proj_b, p_proj);
    }

    // 5-6) finish mean + key norms
    mean_finish_kernel<<<BB, CC>>>();
    key_norm_kernel<<<POOL, CC>>>(pkey);

    // 7) similarity (exact fp32)
    {
        dim3 grid(POOL / 32, BB / 32);
        sim_gemm_kernel<<<grid, 256>>>(p_xnorm, p_pnorm, p_sim);
    }

    // 8-9) top-8 + reduce_sim
    topk_kernel<<<BB, 256>>>();
    reduce_sim_kernel<<<1, 256>>>(out);

    // 10) gather selected projected prompts into output rows 1..64
    {
        dim3 grid(KSEL * PLEN, BB);
        gather_kernel<<<grid, 192>>>(out);
    }
}

// round 6
// speedup vs baseline: 2.7010x; 1.0044x over previous
#include <cuda_runtime.h>
#include <cuda_fp16.h>
#include <math.h>
#include <stdint.h>

// Problem constants
#define BB      256
#define NTOK    197
#define CC      768
#define POOL    1024
#define PLEN    8
#define KSEL    8
#define OUTROWS 261
#define PROMPTED_ELEMS ((size_t)BB * OUTROWS * CC)

#define PROJ_M  (POOL * PLEN)   // 8192
#define NCHUNK  8

// Proj GEMM config (fp16 mma.m16n8k16 + ldmatrix)
#define PBM 64
#define PBN 128
#define PBKH 64                        // halves per kblock (128B rows)
#define PNKB (CC / PBKH)               // 12
#define STAGE_BYTES ((PBM + PBN) * 128)  // 24576
#define PSTAGES 3
#define PROJ_SMEM (PSTAGES * STAGE_BYTES)   // 73728 B -> 3 CTAs/SM

// Scratch (device globals)
__device__ float  g_xnorm[BB * CC];
__device__ float  g_pnorm[POOL * CC];
__device__ float  g_sim[BB * POOL];
__device__ float  g_proj[PROJ_M * CC];
__device__ __half g_ah[PROJ_M * CC];
__device__ __half g_wh[CC * CC];
__device__ float  g_msum[BB * NCHUNK * CC];
__device__ int    g_idx[BB * KSEL];
__device__ float  g_topsum[BB];

// ---------------------------------------------------------------------------
__device__ __forceinline__ uint32_t smem_u32(const void* p) {
    uint32_t a;
    asm("{ .reg .u64 t; cvta.to.shared.u64 t, %1; cvt.u32.u64 %0, t; }"
        : "=r"(a) : "l"(p));
    return a;
}

// ---------------------------------------------------------------------------
__global__ void f32_to_f16_kernel(const float* __restrict__ in,
                                  __half* __restrict__ outp, int n8) {
    int i = blockIdx.x * blockDim.x + threadIdx.x;
    if (i < n8) {
        const float4* p = (const float4*)in + (size_t)i * 2;
        float4 a = p[0], b = p[1];
        __half2 h[4];
        h[0] = __floats2half2_rn(a.x, a.y);
        h[1] = __floats2half2_rn(a.z, a.w);
        h[2] = __floats2half2_rn(b.x, b.y);
        h[3] = __floats2half2_rn(b.z, b.w);
        *(uint4*)((char*)outp + (size_t)i * 16) = *(uint4*)h;
    }
}

// ---------------------------------------------------------------------------
// Proj GEMM: C[m,n] = sum_k Ah[m,k]*Wh[n,k] + bias[n] + Ares[m,n]
//   CTA 64x128, 8 warps 2(m) x 4(n), warp tile 32x32. 3-stage cp.async.
//   72KB smem -> 3 CTAs/SM. grid (6,128) = 768 CTAs.
// ---------------------------------------------------------------------------
__global__ __launch_bounds__(256, 3)
void proj_fp16_kernel(const __half* __restrict__ Ah, const __half* __restrict__ Wh,
                      const float* __restrict__ Ares, const float* __restrict__ bias,
                      float* __restrict__ Cm) {
    extern __shared__ char sm[];
    const uint32_t smbase = smem_u32(sm);

    const int tid  = threadIdx.x;
    const int lane = tid & 31;
    const int wid  = tid >> 5;
    const int wm   = wid >> 2;    // 0..1
    const int wn   = wid & 3;     // 0..3
    const int m0   = blockIdx.y * PBM;
    const int n0   = blockIdx.x * PBN;

    const int crow0 = tid >> 3;   // 0..31
    const int cch   = tid & 7;

    float acc[2][4][4];
    #pragma unroll
    for (int mi = 0; mi < 2; mi++)
        #pragma unroll
        for (int nt = 0; nt < 4; nt++)
            #pragma unroll
            for (int q = 0; q < 4; q++) acc[mi][nt][q] = 0.0f;

    auto issue = [&](int kb) {
        uint32_t stage = smbase + (uint32_t)((kb % PSTAGES) * STAGE_BYTES);
        #pragma unroll
        for (int i = 0; i < 6; i++) {
            int row = crow0 + i * 32;     // 0..191
            const __half* src = (row < PBM)
                ? (Ah + (size_t)(m0 + row) * CC + kb * PBKH + cch * 8)
                : (Wh + (size_t)(n0 + row - PBM) * CC + kb * PBKH + cch * 8);
            uint32_t dst = stage + (uint32_t)row * 128u
                         + (uint32_t)((cch ^ (row & 7)) << 4);
            asm volatile("cp.async.cg.shared.global [%0], [%1], 16;"
                         :: "r"(dst), "l"(src) : "memory");
        }
        asm volatile("cp.async.commit_group;" ::: "memory");
    };

    issue(0);
    issue(1);

    const int q = lane >> 3;   // 0..3
    const int r = lane & 7;

    for (int kb = 0; kb < PNKB; kb++) {
        if (kb + 1 < PNKB) {
            asm volatile("cp.async.wait_group 1;" ::: "memory");
        } else {
            asm volatile("cp.async.wait_group 0;" ::: "memory");
        }
        __syncthreads();
        if (kb + 2 < PNKB) issue(kb + 2);

        const uint32_t Ab = smbase + (uint32_t)((kb % PSTAGES) * STAGE_BYTES);
        const uint32_t Bb = Ab + (uint32_t)(PBM * 128);

        #pragma unroll
        for (int ks = 0; ks < 4; ks++) {
            const int cb = ks * 2 + (q >> 1);
            uint32_t a[2][4];
            #pragma unroll
            for (int mi = 0; mi < 2; mi++) {
                int row = wm * 32 + mi * 16 + (q & 1) * 8 + r;
                uint32_t addr = Ab + (uint32_t)row * 128u
                              + (uint32_t)((cb ^ (row & 7)) << 4);
                asm volatile("ldmatrix.sync.aligned.m8n8.x4.shared.b16 "
                             "{%0,%1,%2,%3}, [%4];"
                             : "=r"(a[mi][0]), "=r"(a[mi][1]),
                               "=r"(a[mi][2]), "=r"(a[mi][3])
                             : "r"(addr));
            }
            uint32_t b[4][2];
            #pragma unroll
            for (int nj = 0; nj < 2; nj++) {
                int row = wn * 32 + nj * 16 + (q & 1) * 8 + r;
                uint32_t addr = Bb + (uint32_t)row * 128u
                              + (uint32_t)((cb ^ (row & 7)) << 4);
                uint32_t r0, r1, r2, r3;
                asm volatile("ldmatrix.sync.aligned.m8n8.x4.shared.b16 "
                             "{%0,%1,%2,%3}, [%4];"
                             : "=r"(r0), "=r"(r1), "=r"(r2), "=r"(r3)
                             : "r"(addr));
                b[nj * 2 + 0][0] = r0; b[nj * 2 + 0][1] = r2;
                b[nj * 2 + 1][0] = r1; b[nj * 2 + 1][1] = r3;
            }
            #pragma unroll
            for (int mi = 0; mi < 2; mi++)
                #pragma unroll
                for (int nt = 0; nt < 4; nt++) {
                    asm volatile(
                        "mma.sync.aligned.m16n8k16.row.col.f32.f16.f16.f32 "
                        "{%0,%1,%2,%3}, {%4,%5,%6,%7}, {%8,%9}, {%0,%1,%2,%3};"
                        : "+f"(acc[mi][nt][0]), "+f"(acc[mi][nt][1]),
                          "+f"(acc[mi][nt][2]), "+f"(acc[mi][nt][3])
                        : "r"(a[mi][0]), "r"(a[mi][1]), "r"(a[mi][2]), "r"(a[mi][3]),
                          "r"(b[nt][0]), "r"(b[nt][1]));
                }
        }
    }

    // epilogue: + bias[n] + Ares[m][n]
    #pragma unroll
    for (int mi = 0; mi < 2; mi++) {
        int r0 = m0 + wm * 32 + mi * 16 + (lane >> 2);
        int r1 = r0 + 8;
        #pragma unroll
        for (int nt = 0; nt < 4; nt++) {
            int n = n0 + wn * 32 + nt * 8 + (lane & 3) * 2;
            {
                float2 res = *(const float2*)(Ares + (size_t)r0 * CC + n);
                float2 bs  = *(const float2*)(bias + n);
                float2 v;
                v.x = acc[mi][nt][0] + bs.x + res.x;
                v.y = acc[mi][nt][1] + bs.y + res.y;
                *(float2*)(Cm + (size_t)r0 * CC + n) = v;
            }
            {
                float2 res = *(const float2*)(Ares + (size_t)r1 * CC + n);
                float2 bs  = *(const float2*)(bias + n);
                float2 v;
                v.x = acc[mi][nt][2] + bs.x + res.x;
                v.y = acc[mi][nt][3] + bs.y + res.y;
                *(float2*)(Cm + (size_t)r1 * CC + n) = v;
            }
        }
    }
}

// ---------------------------------------------------------------------------
// Fused copy + partial mean
// ---------------------------------------------------------------------------
__global__ void copy_mean_kernel(const float* __restrict__ x, float* __restrict__ out) {
    const int ch = blockIdx.x;
    const int b  = blockIdx.y;
    const int t  = threadIdx.x;

    const int t0 = ch * 25;
    const int t1 = (t0 + 25 < NTOK) ? t0 + 25 : NTOK;

    float4 acc = make_float4(0.f, 0.f, 0.f, 0.f);
    const float4* xb = (const float4*)(x + (size_t)b * NTOK * CC);
    float4* ob = (float4*)(out + (size_t)b * OUTROWS * CC);

    for (int tok = t0; tok < t1; tok++) {
        float4 v = xb[(size_t)tok * (CC / 4) + t];
        acc.x += v.x; acc.y += v.y; acc.z += v.z; acc.w += v.w;
        int orow = (tok == 0) ? 0 : tok + KSEL * PLEN;
        ob[(size_t)orow * (CC / 4) + t] = v;
    }
    ((float4*)g_msum)[((size_t)b * NCHUNK + ch) * (CC / 4) + t] = acc;
}

// ---------------------------------------------------------------------------
__global__ void mean_finish_kernel() {
    int b = blockIdx.x;
    int c = threadIdx.x;
    float s = 0.0f;
    #pragma unroll
    for (int ch = 0; ch < NCHUNK; ch++)
        s += g_msum[((size_t)b * NCHUNK + ch) * CC + c];
    float m = s / (float)NTOK;

    __shared__ float sh[CC];
    sh[c] = m * m;
    __syncthreads();
    if (c < 256) sh[c] += sh[c + 256] + sh[c + 512];
    __syncthreads();
    for (int off = 128; off > 0; off >>= 1) {
        if (c < off) sh[c] += sh[c + off];
        __syncthreads();
    }
    __shared__ float rinv;
    if (c == 0) rinv = rsqrtf(fmaxf(sh[0], 1e-12f));
    __syncthreads();
    g_xnorm[b * CC + c] = m * rinv;
}

// ---------------------------------------------------------------------------
__global__ void key_norm_kernel(const float* __restrict__ pk) {
    int p = blockIdx.x;
    int c = threadIdx.x;
    float v = pk[(size_t)p * CC + c];

    __shared__ float sh[CC];
    sh[c] = v * v;
    __syncthreads();
    if (c < 256) sh[c] += sh[c + 256] + sh[c + 512];
    __syncthreads();
    for (int off = 128; off > 0; off >>= 1) {
        if (c < off) sh[c] += sh[c + off];
        __syncthreads();
    }
    __shared__ float rinv;
    if (c == 0) rinv = rsqrtf(fmaxf(sh[0], 1e-12f));
    __syncthreads();
    g_pnorm[p * CC + c] = v * rinv;
}

// ---------------------------------------------------------------------------
// Sim GEMM (fp32 SIMT exact, register-prefetch double-buffer)
// ---------------------------------------------------------------------------
__global__ __launch_bounds__(256)
void sim_gemm_kernel(const float* __restrict__ A, const float* __restrict__ Bm,
                     float* __restrict__ Cm) {
    __shared__ float As[32][33];
    __shared__ float Bs[32][33];

    const int tid = threadIdx.x;
    const int tx = tid & 15;
    const int ty = tid >> 4;
    const int m0 = blockIdx.y * 32;
    const int n0 = blockIdx.x * 32;

    const int lrow = tid >> 3;
    const int lk   = (tid & 7) * 4;

    const float* ag = A  + (size_t)(m0 + lrow) * CC + lk;
    const float* bg = Bm + (size_t)(n0 + lrow) * CC + lk;

    float acc[2][2] = {{0.f,0.f},{0.f,0.f}};

    float4 pa = *(const float4*)(ag);
    float4 pb = *(const float4*)(bg);

    for (int kb = 0; kb < CC / 32; kb++) {
        __syncthreads();
        As[lrow][lk+0]=pa.x; As[lrow][lk+1]=pa.y; As[lrow][lk+2]=pa.z; As[lrow][lk+3]=pa.w;
        Bs[lrow][lk+0]=pb.x; Bs[lrow][lk+1]=pb.y; Bs[lrow][lk+2]=pb.z; Bs[lrow][lk+3]=pb.w;
        __syncthreads();
        if (kb + 1 < CC / 32) {
            pa = *(const float4*)(ag + (kb + 1) * 32);
            pb = *(const float4*)(bg + (kb + 1) * 32);
        }
        #pragma unroll
        for (int kk = 0; kk < 32; kk++) {
            float a0 = As[ty*2+0][kk], a1 = As[ty*2+1][kk];
            float b0 = Bs[tx*2+0][kk], b1 = Bs[tx*2+1][kk];
            acc[0][0] = fmaf(a0,b0,acc[0][0]);
            acc[0][1] = fmaf(a0,b1,acc[0][1]);
            acc[1][0] = fmaf(a1,b0,acc[1][0]);
            acc[1][1] = fmaf(a1,b1,acc[1][1]);
        }
    }
    #pragma unroll
    for (int i = 0; i < 2; i++)
        #pragma unroll
        for (int j = 0; j < 2; j++)
            Cm[(size_t)(m0 + ty*2 + i) * POOL + n0 + tx*2 + j] = acc[i][j];
}

// ---------------------------------------------------------------------------
__global__ void topk_kernel() {
    int b = blockIdx.x;
    int t = threadIdx.x;
    __shared__ float vals[POOL];
    __shared__ float rv[256];
    __shared__ int   ri[256];

    for (int p = t; p < POOL; p += 256) vals[p] = g_sim[b * POOL + p];
    __syncthreads();

    float tsum = 0.0f;
    for (int it = 0; it < KSEL; it++) {
        float bvv = -1e30f; int bii = 0x7fffffff;
        for (int p = t; p < POOL; p += 256) {
            float v = vals[p];
            if (v > bvv || (v == bvv && p < bii)) { bvv = v; bii = p; }
        }
        rv[t] = bvv; ri[t] = bii;
        __syncthreads();
        for (int off = 128; off > 0; off >>= 1) {
            if (t < off) {
                float v2 = rv[t + off]; int i2 = ri[t + off];
                if (v2 > rv[t] || (v2 == rv[t] && i2 < ri[t])) { rv[t] = v2; ri[t] = i2; }
            }
            __syncthreads();
        }
        if (t == 0) {
            g_idx[b * KSEL + it] = ri[0];
            tsum += rv[0];
            vals[ri[0]] = -1e30f;
        }
        __syncthreads();
    }
    if (t == 0) g_topsum[b] = tsum;
}

// ---------------------------------------------------------------------------
__global__ void reduce_sim_kernel(float* __restrict__ out) {
    __shared__ float sh[256];
    int t = threadIdx.x;
    sh[t] = g_topsum[t];
    __syncthreads();
    for (int off = 128; off > 0; off >>= 1) {
        if (t < off) sh[t] += sh[t + off];
        __syncthreads();
    }
    if (t == 0) out[PROMPTED_ELEMS] = sh[0] / (float)BB;
}

// ---------------------------------------------------------------------------
__global__ void gather_kernel(float* __restrict__ out) {
    int j = blockIdx.x;
    int b = blockIdx.y;
    int t = threadIdx.x;

    int pid = g_idx[b * KSEL + (j >> 3)];
    const float4* src = (const float4*)(g_proj + ((size_t)pid * PLEN + (j & 7)) * CC);
    float4 v = src[t];
    ((float4*)(out + ((size_t)b * OUTROWS + 1 + j) * CC))[t] = v;
}

// ---------------------------------------------------------------------------
extern "C" void kernel_launch(void* const* d_in, const int* in_sizes, int n_in,
                              void* d_out, int out_size) {
    const float* x_embed = (const float*)d_in[0];
    const float* prompt  = (const float*)d_in[1];
    const float* pkey    = (const float*)d_in[2];
    const float* proj_w  = (const float*)d_in[3];
    const float* proj_b  = (const float*)d_in[4];
    float* out = (float*)d_out;

    float *p_xnorm, *p_pnorm, *p_sim, *p_proj;
    __half *p_ah, *p_wh;
    cudaGetSymbolAddress((void**)&p_xnorm, g_xnorm);
    cudaGetSymbolAddress((void**)&p_pnorm, g_pnorm);
    cudaGetSymbolAddress((void**)&p_sim,   g_sim);
    cudaGetSymbolAddress((void**)&p_proj,  g_proj);
    cudaGetSymbolAddress((void**)&p_ah,    g_ah);
    cudaGetSymbolAddress((void**)&p_wh,    g_wh);

    // 1-2) convert prompt & W to fp16
    {
        int n8a = PROJ_M * CC / 8;
        f32_to_f16_kernel<<<(n8a + 255) / 256, 256>>>(prompt, p_ah, n8a);
        int n8w = CC * CC / 8;
        f32_to_f16_kernel<<<(n8w + 255) / 256, 256>>>(proj_w, p_wh, n8w);
    }

    // 3) fused copy + partial mean
    {
        dim3 grid(NCHUNK, BB);
        copy_mean_kernel<<<grid, 192>>>(x_embed, out);
    }

    // 4) proj GEMM (fp16 mma + ldmatrix, 64x128 tiles, 3 CTA/SM)
    {
        cudaFuncSetAttribute(proj_fp16_kernel,
                             cudaFuncAttributeMaxDynamicSharedMemorySize, PROJ_SMEM);
        dim3 grid(CC / PBN, PROJ_M / PBM);   // (6, 128) = 768 CTAs
        proj_fp16_kernel<<<grid, 256, PROJ_SMEM>>>(p_ah, p_wh, prompt, proj_b, p_proj);
    }

    // 5-6) finish mean + key norms
    mean_finish_kernel<<<BB, CC>>>();
    key_norm_kernel<<<POOL, CC>>>(pkey);

    // 7) similarity (exact fp32, register-prefetch)
    {
        dim3 grid(POOL / 32, BB / 32);
        sim_gemm_kernel<<<grid, 256>>>(p_xnorm, p_pnorm, p_sim);
    }

    // 8-9) top-8 + reduce_sim
    topk_kernel<<<BB, 256>>>();
    reduce_sim_kernel<<<1, 256>>>(out);

    // 10) gather selected projected prompts into output rows 1..64
    {
        dim3 grid(KSEL * PLEN, BB);
        gather_kernel<<<grid, 192>>>(out);
    }
}

// round 7
// speedup vs baseline: 2.7292x; 1.0104x over previous
#include <cuda_runtime.h>
#include <cuda_fp16.h>
#include <math.h>
#include <stdint.h>

// Problem constants
#define BB      256
#define NTOK    197
#define CC      768
#define POOL    1024
#define PLEN    8
#define KSEL    8
#define OUTROWS 261
#define PROMPTED_ELEMS ((size_t)BB * OUTROWS * CC)

#define PROJ_M  (POOL * PLEN)   // 8192
#define NCHUNK  8

// Proj GEMM config (fp16 mma.m16n8k16 + ldmatrix)
#define PBM 64
#define PBN 128
#define PBKH 64                        // halves per kblock (128B rows)
#define PNKB (CC / PBKH)               // 12
#define STAGE_BYTES ((PBM + PBN) * 128)  // 24576
#define PSTAGES 3
#define PROJ_SMEM (PSTAGES * STAGE_BYTES)   // 73728 B -> 3 CTAs/SM

// Scratch (device globals)
__device__ float  g_xnorm[BB * CC];
__device__ float  g_pnorm[POOL * CC];
__device__ float  g_sim[BB * POOL];
__device__ float  g_proj[PROJ_M * CC];
__device__ __half g_ah[PROJ_M * CC];
__device__ __half g_wh[CC * CC];
__device__ float  g_msum[BB * NCHUNK * CC];
__device__ int    g_idx[BB * KSEL];
__device__ float  g_topsum[BB];

// ---------------------------------------------------------------------------
__device__ __forceinline__ uint32_t smem_u32(const void* p) {
    uint32_t a;
    asm("{ .reg .u64 t; cvta.to.shared.u64 t, %1; cvt.u32.u64 %0, t; }"
        : "=r"(a) : "l"(p));
    return a;
}

// ---------------------------------------------------------------------------
__global__ void f32_to_f16_kernel(const float* __restrict__ in,
                                  __half* __restrict__ outp, int n8) {
    int i = blockIdx.x * blockDim.x + threadIdx.x;
    if (i < n8) {
        const float4* p = (const float4*)in + (size_t)i * 2;
        float4 a = p[0], b = p[1];
        __half2 h[4];
        h[0] = __floats2half2_rn(a.x, a.y);
        h[1] = __floats2half2_rn(a.z, a.w);
        h[2] = __floats2half2_rn(b.x, b.y);
        h[3] = __floats2half2_rn(b.z, b.w);
        *(uint4*)((char*)outp + (size_t)i * 16) = *(uint4*)h;
    }
}

// ---------------------------------------------------------------------------
// Proj GEMM: C[m,n] = sum_k Ah[m,k]*Wh[n,k] + bias[n] + Ares[m,n]
//   CTA 64x128, 8 warps 2(m) x 4(n), warp tile 32x32. 3-stage cp.async.
// ---------------------------------------------------------------------------
__global__ __launch_bounds__(256, 3)
void proj_fp16_kernel(const __half* __restrict__ Ah, const __half* __restrict__ Wh,
                      const float* __restrict__ Ares, const float* __restrict__ bias,
                      float* __restrict__ Cm) {
    extern __shared__ char sm[];
    const uint32_t smbase = smem_u32(sm);

    const int tid  = threadIdx.x;
    const int lane = tid & 31;
    const int wid  = tid >> 5;
    const int wm   = wid >> 2;    // 0..1
    const int wn   = wid & 3;     // 0..3
    const int m0   = blockIdx.y * PBM;
    const int n0   = blockIdx.x * PBN;

    const int crow0 = tid >> 3;
    const int cch   = tid & 7;

    float acc[2][4][4];
    #pragma unroll
    for (int mi = 0; mi < 2; mi++)
        #pragma unroll
        for (int nt = 0; nt < 4; nt++)
            #pragma unroll
            for (int q = 0; q < 4; q++) acc[mi][nt][q] = 0.0f;

    auto issue = [&](int kb) {
        uint32_t stage = smbase + (uint32_t)((kb % PSTAGES) * STAGE_BYTES);
        #pragma unroll
        for (int i = 0; i < 6; i++) {
            int row = crow0 + i * 32;
            const __half* src = (row < PBM)
                ? (Ah + (size_t)(m0 + row) * CC + kb * PBKH + cch * 8)
                : (Wh + (size_t)(n0 + row - PBM) * CC + kb * PBKH + cch * 8);
            uint32_t dst = stage + (uint32_t)row * 128u
                         + (uint32_t)((cch ^ (row & 7)) << 4);
            asm volatile("cp.async.cg.shared.global [%0], [%1], 16;"
                         :: "r"(dst), "l"(src) : "memory");
        }
        asm volatile("cp.async.commit_group;" ::: "memory");
    };

    issue(0);
    issue(1);

    const int q = lane >> 3;
    const int r = lane & 7;

    for (int kb = 0; kb < PNKB; kb++) {
        if (kb + 1 < PNKB) {
            asm volatile("cp.async.wait_group 1;" ::: "memory");
        } else {
            asm volatile("cp.async.wait_group 0;" ::: "memory");
        }
        __syncthreads();
        if (kb + 2 < PNKB) issue(kb + 2);

        const uint32_t Ab = smbase + (uint32_t)((kb % PSTAGES) * STAGE_BYTES);
        const uint32_t Bb = Ab + (uint32_t)(PBM * 128);

        #pragma unroll
        for (int ks = 0; ks < 4; ks++) {
            const int cb = ks * 2 + (q >> 1);
            uint32_t a[2][4];
            #pragma unroll
            for (int mi = 0; mi < 2; mi++) {
                int row = wm * 32 + mi * 16 + (q & 1) * 8 + r;
                uint32_t addr = Ab + (uint32_t)row * 128u
                              + (uint32_t)((cb ^ (row & 7)) << 4);
                asm volatile("ldmatrix.sync.aligned.m8n8.x4.shared.b16 "
                             "{%0,%1,%2,%3}, [%4];"
                             : "=r"(a[mi][0]), "=r"(a[mi][1]),
                               "=r"(a[mi][2]), "=r"(a[mi][3])
                             : "r"(addr));
            }
            uint32_t b[4][2];
            #pragma unroll
            for (int nj = 0; nj < 2; nj++) {
                int row = wn * 32 + nj * 16 + (q & 1) * 8 + r;
                uint32_t addr = Bb + (uint32_t)row * 128u
                              + (uint32_t)((cb ^ (row & 7)) << 4);
                uint32_t r0, r1, r2, r3;
                asm volatile("ldmatrix.sync.aligned.m8n8.x4.shared.b16 "
                             "{%0,%1,%2,%3}, [%4];"
                             : "=r"(r0), "=r"(r1), "=r"(r2), "=r"(r3)
                             : "r"(addr));
                b[nj * 2 + 0][0] = r0; b[nj * 2 + 0][1] = r2;
                b[nj * 2 + 1][0] = r1; b[nj * 2 + 1][1] = r3;
            }
            #pragma unroll
            for (int mi = 0; mi < 2; mi++)
                #pragma unroll
                for (int nt = 0; nt < 4; nt++) {
                    asm volatile(
                        "mma.sync.aligned.m16n8k16.row.col.f32.f16.f16.f32 "
                        "{%0,%1,%2,%3}, {%4,%5,%6,%7}, {%8,%9}, {%0,%1,%2,%3};"
                        : "+f"(acc[mi][nt][0]), "+f"(acc[mi][nt][1]),
                          "+f"(acc[mi][nt][2]), "+f"(acc[mi][nt][3])
                        : "r"(a[mi][0]), "r"(a[mi][1]), "r"(a[mi][2]), "r"(a[mi][3]),
                          "r"(b[nt][0]), "r"(b[nt][1]));
                }
        }
    }

    #pragma unroll
    for (int mi = 0; mi < 2; mi++) {
        int r0 = m0 + wm * 32 + mi * 16 + (lane >> 2);
        int r1 = r0 + 8;
        #pragma unroll
        for (int nt = 0; nt < 4; nt++) {
            int n = n0 + wn * 32 + nt * 8 + (lane & 3) * 2;
            {
                float2 res = *(const float2*)(Ares + (size_t)r0 * CC + n);
                float2 bs  = *(const float2*)(bias + n);
                float2 v;
                v.x = acc[mi][nt][0] + bs.x + res.x;
                v.y = acc[mi][nt][1] + bs.y + res.y;
                *(float2*)(Cm + (size_t)r0 * CC + n) = v;
            }
            {
                float2 res = *(const float2*)(Ares + (size_t)r1 * CC + n);
                float2 bs  = *(const float2*)(bias + n);
                float2 v;
                v.x = acc[mi][nt][2] + bs.x + res.x;
                v.y = acc[mi][nt][3] + bs.y + res.y;
                *(float2*)(Cm + (size_t)r1 * CC + n) = v;
            }
        }
    }
}

// ---------------------------------------------------------------------------
__global__ void copy_mean_kernel(const float* __restrict__ x, float* __restrict__ out) {
    const int ch = blockIdx.x;
    const int b  = blockIdx.y;
    const int t  = threadIdx.x;

    const int t0 = ch * 25;
    const int t1 = (t0 + 25 < NTOK) ? t0 + 25 : NTOK;

    float4 acc = make_float4(0.f, 0.f, 0.f, 0.f);
    const float4* xb = (const float4*)(x + (size_t)b * NTOK * CC);
    float4* ob = (float4*)(out + (size_t)b * OUTROWS * CC);

    for (int tok = t0; tok < t1; tok++) {
        float4 v = xb[(size_t)tok * (CC / 4) + t];
        acc.x += v.x; acc.y += v.y; acc.z += v.z; acc.w += v.w;
        int orow = (tok == 0) ? 0 : tok + KSEL * PLEN;
        ob[(size_t)orow * (CC / 4) + t] = v;
    }
    ((float4*)g_msum)[((size_t)b * NCHUNK + ch) * (CC / 4) + t] = acc;
}

// ---------------------------------------------------------------------------
__global__ void mean_finish_kernel() {
    int b = blockIdx.x;
    int c = threadIdx.x;
    float s = 0.0f;
    #pragma unroll
    for (int ch = 0; ch < NCHUNK; ch++)
        s += g_msum[((size_t)b * NCHUNK + ch) * CC + c];
    float m = s / (float)NTOK;

    __shared__ float sh[CC];
    sh[c] = m * m;
    __syncthreads();
    if (c < 256) sh[c] += sh[c + 256] + sh[c + 512];
    __syncthreads();
    for (int off = 128; off > 0; off >>= 1) {
        if (c < off) sh[c] += sh[c + off];
        __syncthreads();
    }
    __shared__ float rinv;
    if (c == 0) rinv = rsqrtf(fmaxf(sh[0], 1e-12f));
    __syncthreads();
    g_xnorm[b * CC + c] = m * rinv;
}

// ---------------------------------------------------------------------------
__global__ void key_norm_kernel(const float* __restrict__ pk) {
    int p = blockIdx.x;
    int c = threadIdx.x;
    float v = pk[(size_t)p * CC + c];

    __shared__ float sh[CC];
    sh[c] = v * v;
    __syncthreads();
    if (c < 256) sh[c] += sh[c + 256] + sh[c + 512];
    __syncthreads();
    for (int off = 128; off > 0; off >>= 1) {
        if (c < off) sh[c] += sh[c + off];
        __syncthreads();
    }
    __shared__ float rinv;
    if (c == 0) rinv = rsqrtf(fmaxf(sh[0], 1e-12f));
    __syncthreads();
    g_pnorm[p * CC + c] = v * rinv;
}

// ---------------------------------------------------------------------------
__global__ __launch_bounds__(256)
void sim_gemm_kernel(const float* __restrict__ A, const float* __restrict__ Bm,
                     float* __restrict__ Cm) {
    __shared__ float As[32][33];
    __shared__ float Bs[32][33];

    const int tid = threadIdx.x;
    const int tx = tid & 15;
    const int ty = tid >> 4;
    const int m0 = blockIdx.y * 32;
    const int n0 = blockIdx.x * 32;

    const int lrow = tid >> 3;
    const int lk   = (tid & 7) * 4;

    const float* ag = A  + (size_t)(m0 + lrow) * CC + lk;
    const float* bg = Bm + (size_t)(n0 + lrow) * CC + lk;

    float acc[2][2] = {{0.f,0.f},{0.f,0.f}};

    float4 pa = *(const float4*)(ag);
    float4 pb = *(const float4*)(bg);

    for (int kb = 0; kb < CC / 32; kb++) {
        __syncthreads();
        As[lrow][lk+0]=pa.x; As[lrow][lk+1]=pa.y; As[lrow][lk+2]=pa.z; As[lrow][lk+3]=pa.w;
        Bs[lrow][lk+0]=pb.x; Bs[lrow][lk+1]=pb.y; Bs[lrow][lk+2]=pb.z; Bs[lrow][lk+3]=pb.w;
        __syncthreads();
        if (kb + 1 < CC / 32) {
            pa = *(const float4*)(ag + (kb + 1) * 32);
            pb = *(const float4*)(bg + (kb + 1) * 32);
        }
        #pragma unroll
        for (int kk = 0; kk < 32; kk++) {
            float a0 = As[ty*2+0][kk], a1 = As[ty*2+1][kk];
            float b0 = Bs[tx*2+0][kk], b1 = Bs[tx*2+1][kk];
            acc[0][0] = fmaf(a0,b0,acc[0][0]);
            acc[0][1] = fmaf(a0,b1,acc[0][1]);
            acc[1][0] = fmaf(a1,b0,acc[1][0]);
            acc[1][1] = fmaf(a1,b1,acc[1][1]);
        }
    }
    #pragma unroll
    for (int i = 0; i < 2; i++)
        #pragma unroll
        for (int j = 0; j < 2; j++)
            Cm[(size_t)(m0 + ty*2 + i) * POOL + n0 + tx*2 + j] = acc[i][j];
}

// ---------------------------------------------------------------------------
__global__ void topk_kernel() {
    int b = blockIdx.x;
    int t = threadIdx.x;
    __shared__ float vals[POOL];
    __shared__ float rv[256];
    __shared__ int   ri[256];

    for (int p = t; p < POOL; p += 256) vals[p] = g_sim[b * POOL + p];
    __syncthreads();

    float tsum = 0.0f;
    for (int it = 0; it < KSEL; it++) {
        float bvv = -1e30f; int bii = 0x7fffffff;
        for (int p = t; p < POOL; p += 256) {
            float v = vals[p];
            if (v > bvv || (v == bvv && p < bii)) { bvv = v; bii = p; }
        }
        rv[t] = bvv; ri[t] = bii;
        __syncthreads();
        for (int off = 128; off > 0; off >>= 1) {
            if (t < off) {
                float v2 = rv[t + off]; int i2 = ri[t + off];
                if (v2 > rv[t] || (v2 == rv[t] && i2 < ri[t])) { rv[t] = v2; ri[t] = i2; }
            }
            __syncthreads();
        }
        if (t == 0) {
            g_idx[b * KSEL + it] = ri[0];
            tsum += rv[0];
            vals[ri[0]] = -1e30f;
        }
        __syncthreads();
    }
    if (t == 0) g_topsum[b] = tsum;
}

// ---------------------------------------------------------------------------
__global__ void reduce_sim_kernel(float* __restrict__ out) {
    __shared__ float sh[256];
    int t = threadIdx.x;
    sh[t] = g_topsum[t];
    __syncthreads();
    for (int off = 128; off > 0; off >>= 1) {
        if (t < off) sh[t] += sh[t + off];
        __syncthreads();
    }
    if (t == 0) out[PROMPTED_ELEMS] = sh[0] / (float)BB;
}

// ---------------------------------------------------------------------------
__global__ void gather_kernel(float* __restrict__ out) {
    int j = blockIdx.x;
    int b = blockIdx.y;
    int t = threadIdx.x;

    int pid = g_idx[b * KSEL + (j >> 3)];
    const float4* src = (const float4*)(g_proj + ((size_t)pid * PLEN + (j & 7)) * CC);
    float4 v = src[t];
    ((float4*)(out + ((size_t)b * OUTROWS + 1 + j) * CC))[t] = v;
}

// ---------------------------------------------------------------------------
extern "C" void kernel_launch(void* const* d_in, const int* in_sizes, int n_in,
                              void* d_out, int out_size) {
    const float* x_embed = (const float*)d_in[0];
    const float* prompt  = (const float*)d_in[1];
    const float* pkey    = (const float*)d_in[2];
    const float* proj_w  = (const float*)d_in[3];
    const float* proj_b  = (const float*)d_in[4];
    float* out = (float*)d_out;

    float *p_xnorm, *p_pnorm, *p_sim, *p_proj;
    __half *p_ah, *p_wh;
    cudaGetSymbolAddress((void**)&p_xnorm, g_xnorm);
    cudaGetSymbolAddress((void**)&p_pnorm, g_pnorm);
    cudaGetSymbolAddress((void**)&p_sim,   g_sim);
    cudaGetSymbolAddress((void**)&p_proj,  g_proj);
    cudaGetSymbolAddress((void**)&p_ah,    g_ah);
    cudaGetSymbolAddress((void**)&p_wh,    g_wh);

    // One-time resources (handles only; no device memory)
    static cudaStream_t sB = nullptr;
    static cudaEvent_t  evFork = nullptr, evJoin = nullptr;
    if (sB == nullptr) {
        cudaStreamCreateWithFlags(&sB, cudaStreamNonBlocking);
        cudaEventCreateWithFlags(&evFork, cudaEventDisableTiming);
        cudaEventCreateWithFlags(&evJoin, cudaEventDisableTiming);
        cudaFuncSetAttribute(proj_fp16_kernel,
                             cudaFuncAttributeMaxDynamicSharedMemorySize, PROJ_SMEM);
    }

    // ---- fork stream B off the capture-origin stream ----
    cudaEventRecord(evFork, 0);
    cudaStreamWaitEvent(sB, evFork, 0);

    // ===== Stream B (tensor/L2-bound chain; only gather depends on it) =====
    {
        int n8a = PROJ_M * CC / 8;
        f32_to_f16_kernel<<<(n8a + 255) / 256, 256, 0, sB>>>(prompt, p_ah, n8a);
        int n8w = CC * CC / 8;
        f32_to_f16_kernel<<<(n8w + 255) / 256, 256, 0, sB>>>(proj_w, p_wh, n8w);
        dim3 grid(CC / PBN, PROJ_M / PBM);   // (6, 128)
        proj_fp16_kernel<<<grid, 256, PROJ_SMEM, sB>>>(p_ah, p_wh, prompt, proj_b, p_proj);
        cudaEventRecord(evJoin, sB);
    }

    // ===== Stream 0 (DRAM-bound critical path) =====
    key_norm_kernel<<<POOL, CC>>>(pkey);
    {
        dim3 grid(NCHUNK, BB);
        copy_mean_kernel<<<grid, 192>>>(x_embed, out);
    }
    mean_finish_kernel<<<BB, CC>>>();
    {
        dim3 grid(POOL / 32, BB / 32);
        sim_gemm_kernel<<<grid, 256>>>(p_xnorm, p_pnorm, p_sim);
    }
    topk_kernel<<<BB, 256>>>();
    reduce_sim_kernel<<<1, 256>>>(out);

    // ---- join: gather needs g_proj (stream B) and g_idx (stream 0) ----
    cudaStreamWaitEvent(0, evJoin, 0);
    {
        dim3 grid(KSEL * PLEN, BB);
        gather_kernel<<<grid, 192>>>(out);
    }
}